// round 9
// baseline (speedup 1.0000x reference)
#include <cuda_runtime.h>
#include <cuda_bf16.h>
#include <cstdint>

// MaskedAttention: B=4, S=1024, WIDTH=1024, H=16, DH=64
// Head-axis softmax FUSED into the QK kernel (softmax axis = heads lives in
// registers). GEMMs: R3-proven bf16 3-term split mma.sync core.

#define B_ 4
#define S_ 1024
#define W_ 1024
#define H_ 16
#define DH_ 64
#define M_ (B_ * S_)

// ---------------- device scratch (allocation-free rule) --------------------
__device__ __nv_bfloat16 g_q_h[M_ * W_], g_q_l[M_ * W_];
__device__ __nv_bfloat16 g_k_h[M_ * W_], g_k_l[M_ * W_];
__device__ float g_vt[B_ * H_ * DH_ * S_];          // V transposed [bh][d][s]
__device__ float g_x[M_ * W_];
__device__ float g_at[(size_t)B_ * H_ * S_ * S_];   // post-softmax attn (fp32)

// ---------------- helpers --------------------------------------------------
__device__ __forceinline__ void mma_bf16(float* c, const uint32_t* a, const uint32_t* b) {
    asm volatile(
        "mma.sync.aligned.m16n8k16.row.col.f32.bf16.bf16.f32 "
        "{%0,%1,%2,%3}, {%4,%5,%6,%7}, {%8,%9}, {%0,%1,%2,%3};"
        : "+f"(c[0]), "+f"(c[1]), "+f"(c[2]), "+f"(c[3])
        : "r"(a[0]), "r"(a[1]), "r"(a[2]), "r"(a[3]), "r"(b[0]), "r"(b[1]));
}

__device__ __forceinline__ void ldsm4(uint32_t* r, uint32_t saddr) {
    asm volatile("ldmatrix.sync.aligned.m8n8.x4.shared.b16 {%0,%1,%2,%3}, [%4];"
                 : "=r"(r[0]), "=r"(r[1]), "=r"(r[2]), "=r"(r[3]) : "r"(saddr));
}

__device__ __forceinline__ void split_pack(float x, float y, uint32_t& hi, uint32_t& lo) {
    __nv_bfloat16 hx = __float2bfloat16(x);
    __nv_bfloat16 hy = __float2bfloat16(y);
    __nv_bfloat16 lx = __float2bfloat16(x - __bfloat162float(hx));
    __nv_bfloat16 ly = __float2bfloat16(y - __bfloat162float(hy));
    __nv_bfloat162 hp = __halves2bfloat162(hx, hy);
    __nv_bfloat162 lp = __halves2bfloat162(lx, ly);
    hi = *reinterpret_cast<uint32_t*>(&hp);
    lo = *reinterpret_cast<uint32_t*>(&lp);
}

#define CP16(dst_u32, src_ptr) \
    asm volatile("cp.async.cg.shared.global [%0], [%1], 16;" :: "r"(dst_u32), "l"(src_ptr))

// ---------------------------------------------------------------------------
// R3 GEMM core (proven 655us): fp32 inputs, in-loop split to bf16 hi/lo smem,
// 3-pass mma (hi*hi + lo*hi + hi*lo), scalar-LDS fragments.
// 128(M) x BN(N) tile, K-tile 32, 256 threads (8 warps: 4m x 2n).
// MODE 0: fp32 C (+bias). MODE 1: split bf16x2 C. MODE 2: vt fp32 scatter.
// ---------------------------------------------------------------------------
template <int BN, int MODE>
__device__ __forceinline__ void gemm_core(
        const float* __restrict__ A, int lda,
        const float* __restrict__ B, int ldb,
        int K, float scale, const float* __restrict__ bias,
        float* __restrict__ Cf, uint32_t* __restrict__ Ch, uint32_t* __restrict__ Cl,
        int ldc, float* __restrict__ vt) {
    constexpr int NT = BN / 16;
    __shared__ uint32_t AsH[128 * 20];
    __shared__ uint32_t AsL[128 * 20];
    __shared__ uint32_t BsH[BN * 20];
    __shared__ uint32_t BsL[BN * 20];

    const int tid = threadIdx.x;
    const int lane = tid & 31, warp = tid >> 5;
    const int gid = lane >> 2, tig = lane & 3;
    const int wm = warp >> 1, wn = warp & 1;
    const int m0w = wm * 32, n0w = wn * (BN / 2);
    const int row0 = blockIdx.y * 128;
    const int col0 = blockIdx.x * BN;

    float acc[2][NT][4] = {};

    for (int k0 = 0; k0 < K; k0 += 32) {
        #pragma unroll
        for (int it = 0; it < 4; it++) {
            int idx = tid + it * 256;
            int r = idx >> 3, kv = idx & 7;
            float4 t = *(const float4*)&A[(size_t)(row0 + r) * lda + k0 + kv * 4];
            uint32_t h0, h1, l0, l1;
            split_pack(t.x, t.y, h0, l0);
            split_pack(t.z, t.w, h1, l1);
            AsH[r * 20 + kv * 2] = h0;  AsH[r * 20 + kv * 2 + 1] = h1;
            AsL[r * 20 + kv * 2] = l0;  AsL[r * 20 + kv * 2 + 1] = l1;
        }
        #pragma unroll
        for (int it = 0; it < BN / 32; it++) {
            int idx = tid + it * 256;
            int r = idx >> 3, kv = idx & 7;
            float4 t = *(const float4*)&B[(size_t)(col0 + r) * ldb + k0 + kv * 4];
            uint32_t h0, h1, l0, l1;
            split_pack(t.x, t.y, h0, l0);
            split_pack(t.z, t.w, h1, l1);
            BsH[r * 20 + kv * 2] = h0;  BsH[r * 20 + kv * 2 + 1] = h1;
            BsL[r * 20 + kv * 2] = l0;  BsL[r * 20 + kv * 2 + 1] = l1;
        }
        __syncthreads();

        #pragma unroll
        for (int ks = 0; ks < 2; ks++) {
            const int kb = ks * 8;
            uint32_t ah[2][4], al[2][4], bh[NT][2];
            #pragma unroll
            for (int mi = 0; mi < 2; mi++) {
                int rb = (m0w + mi * 16 + gid) * 20 + kb;
                ah[mi][0] = AsH[rb + tig];
                ah[mi][1] = AsH[rb + 8 * 20 + tig];
                ah[mi][2] = AsH[rb + tig + 4];
                ah[mi][3] = AsH[rb + 8 * 20 + tig + 4];
                al[mi][0] = AsL[rb + tig];
                al[mi][1] = AsL[rb + 8 * 20 + tig];
                al[mi][2] = AsL[rb + tig + 4];
                al[mi][3] = AsL[rb + 8 * 20 + tig + 4];
            }
            #pragma unroll
            for (int ni = 0; ni < NT; ni++) {
                int rb = (n0w + ni * 8 + gid) * 20 + kb;
                bh[ni][0] = BsH[rb + tig];
                bh[ni][1] = BsH[rb + tig + 4];
            }
            #pragma unroll
            for (int mi = 0; mi < 2; mi++)
                #pragma unroll
                for (int ni = 0; ni < NT; ni++)
                    mma_bf16(acc[mi][ni], ah[mi], bh[ni]);
            #pragma unroll
            for (int mi = 0; mi < 2; mi++)
                #pragma unroll
                for (int ni = 0; ni < NT; ni++)
                    mma_bf16(acc[mi][ni], al[mi], bh[ni]);
            uint32_t bl[NT][2];
            #pragma unroll
            for (int ni = 0; ni < NT; ni++) {
                int rb = (n0w + ni * 8 + gid) * 20 + kb;
                bl[ni][0] = BsL[rb + tig];
                bl[ni][1] = BsL[rb + tig + 4];
            }
            #pragma unroll
            for (int mi = 0; mi < 2; mi++)
                #pragma unroll
                for (int ni = 0; ni < NT; ni++)
                    mma_bf16(acc[mi][ni], ah[mi], bl[ni]);
        }
        __syncthreads();
    }

    #pragma unroll
    for (int mi = 0; mi < 2; mi++) {
        #pragma unroll
        for (int ni = 0; ni < NT; ni++) {
            int row = row0 + m0w + mi * 16 + gid;
            int col = col0 + n0w + ni * 8 + tig * 2;
            float b0 = bias ? bias[col] : 0.0f;
            float b1 = bias ? bias[col + 1] : 0.0f;
            float v0 = acc[mi][ni][0] * scale + b0;
            float v1 = acc[mi][ni][1] * scale + b1;
            float v2 = acc[mi][ni][2] * scale + b0;
            float v3 = acc[mi][ni][3] * scale + b1;
            if (MODE == 0) {
                float2 o0 = {v0, v1}, o1 = {v2, v3};
                *(float2*)&Cf[(size_t)row * ldc + col] = o0;
                *(float2*)&Cf[(size_t)(row + 8) * ldc + col] = o1;
            } else if (MODE == 1) {
                uint32_t h0, l0, h1, l1;
                split_pack(v0, v1, h0, l0);
                split_pack(v2, v3, h1, l1);
                size_t i0 = ((size_t)row * ldc + col) >> 1;
                size_t i1 = ((size_t)(row + 8) * ldc + col) >> 1;
                Ch[i0] = h0; Cl[i0] = l0;
                Ch[i1] = h1; Cl[i1] = l1;
            } else {
                int b = row >> 10, s = row & 1023;
                int h = col >> 6, d = col & 63;
                size_t base = ((size_t)(b * 16 + h) * 64 + d) * S_;
                vt[base + s] = v0;
                vt[base + S_ + s] = v1;
                vt[base + s + 8] = v2;
                vt[base + S_ + s + 8] = v3;
            }
        }
    }
}

// ---------------- kernel wrappers ------------------------------------------
__global__ __launch_bounds__(256) void proj_qk_kernel(
        const float* __restrict__ A, const float* __restrict__ Wt,
        const float* __restrict__ bias, uint32_t* Ch, uint32_t* Cl) {
    gemm_core<128, 1>(A, W_, Wt, W_, W_, 1.0f, bias,
                      nullptr, Ch, Cl, W_, nullptr);
}

__global__ __launch_bounds__(256) void proj_vt_kernel(
        const float* __restrict__ A, const float* __restrict__ Wt,
        const float* __restrict__ bias, float* vt) {
    gemm_core<128, 2>(A, W_, Wt, W_, W_, 1.0f, bias,
                      nullptr, nullptr, nullptr, 0, vt);
}

__global__ __launch_bounds__(256) void av_kernel(
        const float* __restrict__ attn, const float* __restrict__ vt,
        float* __restrict__ x) {
    const int bh = blockIdx.z;
    const int b = bh >> 4, h = bh & 15;
    gemm_core<64, 0>(attn + (size_t)bh * S_ * S_, S_,
                     vt + (size_t)bh * DH_ * S_, S_,
                     S_, 1.0f, nullptr,
                     x + (size_t)b * S_ * W_ + h * DH_, nullptr, nullptr, W_,
                     nullptr);
}

__global__ __launch_bounds__(256) void out_kernel(
        const float* __restrict__ A, const float* __restrict__ Wt,
        const float* __restrict__ bias, float* C) {
    gemm_core<128, 0>(A, W_, Wt, W_, W_, 1.0f, bias,
                      C, nullptr, nullptr, W_, nullptr);
}

// ---------------------------------------------------------------------------
// FUSED QK^T + head-softmax.
// Block: 32(q) x 32(k) tile for ALL 16 heads of one batch.
// 8 warps = 2(q) x 4(k); warp tile per head = 16x8 (one m16n8k16 -> 4 accs).
// Head loop double-buffered via cp.async; softmax over h in registers
// (fragment positions identical across heads). Writes post-softmax attn fp32.
// ---------------------------------------------------------------------------
__global__ __launch_bounds__(256, 2) void qks_kernel(
        const __nv_bfloat16* __restrict__ qh, const __nv_bfloat16* __restrict__ ql,
        const __nv_bfloat16* __restrict__ kh, const __nv_bfloat16* __restrict__ kl,
        const int* __restrict__ mask, float* __restrict__ attn) {
    constexpr int RS = 36;              // u32 row stride (32 data + 4 pad)
    constexpr int CSZ = 32 * RS;        // one component (32 rows)
    constexpr int STG = 4 * CSZ;        // QH QL KH KL
    __shared__ uint32_t sm[2 * STG];    // 36864 B

    const int tid = threadIdx.x, lane = tid & 31, warp = tid >> 5;
    const int wq = warp >> 2, wk = warp & 3;
    const int gid = lane >> 2, tig = lane & 3;
    const int q0 = blockIdx.y * 32, k0 = blockIdx.x * 32, b = blockIdx.z;
    const uint32_t sb = (uint32_t)__cvta_generic_to_shared(sm);

    // cp.async: each quarter of the block loads one component (QH/QL/KH/KL)
    const int comp = tid >> 6;
    const __nv_bfloat16* src = (comp == 0) ? qh : (comp == 1) ? ql
                             : (comp == 2) ? kh : kl;
    const int rbase = (comp < 2) ? q0 : k0;

    // ldmatrix lane addressing
    const int a_row = wq * 16 + (lane & 15);
    const int a_co  = (lane >> 4) * 4;
    const int b_row = wk * 8 + (lane & 7);
    const int b_co  = (lane >> 3) * 4;

    float acc[H_][4];
    #pragma unroll
    for (int h = 0; h < H_; h++) {
        acc[h][0] = 0.f; acc[h][1] = 0.f; acc[h][2] = 0.f; acc[h][3] = 0.f;
    }

    auto load_head = [&](int st, int h) {
        uint32_t dst0 = sb + (uint32_t)(st * STG + comp * CSZ) * 4;
        #pragma unroll
        for (int i = 0; i < 4; i++) {
            int chunk = (tid & 63) * 4 + i;
            int r = chunk >> 3, ck = chunk & 7;
            size_t go = (size_t)(b * S_ + rbase + r) * W_ + h * DH_ + ck * 8;
            CP16(dst0 + (uint32_t)(r * RS + ck * 4) * 4, src + go);
        }
    };

    load_head(0, 0);
    asm volatile("cp.async.commit_group;" ::: "memory");

    #pragma unroll
    for (int h = 0; h < H_; h++) {
        const int st = h & 1;
        if (h + 1 < H_) {
            load_head(st ^ 1, h + 1);
            asm volatile("cp.async.commit_group;" ::: "memory");
            asm volatile("cp.async.wait_group 1;" ::: "memory");
        } else {
            asm volatile("cp.async.wait_group 0;" ::: "memory");
        }
        __syncthreads();

        const uint32_t qb  = sb + (uint32_t)(st * STG) * 4;
        const uint32_t kbb = sb + (uint32_t)(st * STG + 2 * CSZ) * 4;
        #pragma unroll
        for (int ks2 = 0; ks2 < 2; ks2++) {
            uint32_t bh2[4], bl2[4];
            ldsm4(bh2, kbb + (uint32_t)(b_row * RS + ks2 * 16 + b_co) * 4);
            ldsm4(bl2, kbb + (uint32_t)(CSZ + b_row * RS + ks2 * 16 + b_co) * 4);
            #pragma unroll
            for (int ks = 0; ks < 2; ks++) {
                uint32_t ah[4], al[4];
                uint32_t ao = (uint32_t)(a_row * RS + ks2 * 16 + ks * 8 + a_co) * 4;
                ldsm4(ah, qb + ao);
                ldsm4(al, qb + (uint32_t)CSZ * 4 + ao);
                uint32_t bfh[2] = {bh2[ks * 2], bh2[ks * 2 + 1]};
                uint32_t bfl[2] = {bl2[ks * 2], bl2[ks * 2 + 1]};
                mma_bf16(acc[h], ah, bfh);
                mma_bf16(acc[h], al, bfh);
                mma_bf16(acc[h], ah, bfl);
            }
        }
        __syncthreads();
    }

    // ---- head-axis softmax in registers ----
    const int gq0 = q0 + wq * 16 + gid;
    const int gq1 = gq0 + 8;
    const int gk  = k0 + wk * 8 + tig * 2;
    const int2 m0 = *(const int2*)&mask[((size_t)b * S_ + gq0) * S_ + gk];
    const int2 m1 = *(const int2*)&mask[((size_t)b * S_ + gq1) * S_ + gk];
    const int ms[4] = {m0.x, m0.y, m1.x, m1.y};

    #pragma unroll
    for (int j = 0; j < 4; j++) {
        if (ms[j] == 0) {
            #pragma unroll
            for (int h = 0; h < H_; h++) acc[h][j] = 1.0f / 16.0f;
        } else {
            float mx = -1e30f;
            #pragma unroll
            for (int h = 0; h < H_; h++) {
                acc[h][j] *= 0.125f;               // 1/sqrt(64)
                mx = fmaxf(mx, acc[h][j]);
            }
            float s = 0.0f;
            #pragma unroll
            for (int h = 0; h < H_; h++) {
                acc[h][j] = __expf(acc[h][j] - mx);
                s += acc[h][j];
            }
            float inv = 1.0f / s;
            #pragma unroll
            for (int h = 0; h < H_; h++) acc[h][j] *= inv;
        }
    }

    // ---- store post-softmax attn (fp32) ----
    #pragma unroll
    for (int h = 0; h < H_; h++) {
        size_t o = ((size_t)(b * H_ + h) * S_ + gq0) * S_ + gk;
        float2 t0 = {acc[h][0], acc[h][1]};
        float2 t1 = {acc[h][2], acc[h][3]};
        *(float2*)&attn[o] = t0;
        *(float2*)&attn[o + (size_t)8 * S_] = t1;
    }
}

// ---------------------------------------------------------------------------
extern "C" void kernel_launch(void* const* d_in, const int* in_sizes, int n_in,
                              void* d_out, int out_size) {
    const float* inp  = (const float*)d_in[0];
    const int*   mask = (const int*)  d_in[1];
    const float* wq   = (const float*)d_in[2];
    const float* bq   = (const float*)d_in[3];
    const float* wk   = (const float*)d_in[4];
    const float* bk   = (const float*)d_in[5];
    const float* wv   = (const float*)d_in[6];
    const float* bv   = (const float*)d_in[7];
    const float* wo   = (const float*)d_in[8];
    const float* bo   = (const float*)d_in[9];
    float* out = (float*)d_out;

    #define SYM(p, s) void* p; cudaGetSymbolAddress(&p, s)
    SYM(q_h, g_q_h);  SYM(q_l, g_q_l);
    SYM(k_h, g_k_h);  SYM(k_l, g_k_l);
    SYM(vt, g_vt);    SYM(x, g_x);
    SYM(at, g_at);
    #undef SYM

    dim3 pg(W_ / 128, M_ / 128);   // (8, 32)
    // 1) projections: q,k -> split bf16; v -> fp32 transposed vt
    proj_qk_kernel<<<pg, 256>>>(inp, wq, bq, (uint32_t*)q_h, (uint32_t*)q_l);
    proj_qk_kernel<<<pg, 256>>>(inp, wk, bk, (uint32_t*)k_h, (uint32_t*)k_l);
    proj_vt_kernel<<<pg, 256>>>(inp, wv, bv, (float*)vt);

    // 2) fused QK^T + head-softmax -> attn fp32
    dim3 qg(S_ / 32, S_ / 32, B_);   // (32, 32, 4)
    qks_kernel<<<qg, 256>>>(
        (const __nv_bfloat16*)q_h, (const __nv_bfloat16*)q_l,
        (const __nv_bfloat16*)k_h, (const __nv_bfloat16*)k_l,
        mask, (float*)at);

    // 3) attn @ V -> x
    dim3 ag(1, S_ / 128, B_ * H_);   // (1, 8, 64)
    av_kernel<<<ag, 256>>>((const float*)at, (const float*)vt, (float*)x);

    // 4) output projection
    out_kernel<<<pg, 256>>>((const float*)x, wo, bo, out);
}

// round 11
// speedup vs baseline: 1.8852x; 1.8852x over previous
#include <cuda_runtime.h>
#include <cuda_bf16.h>
#include <cuda_fp16.h>
#include <cstdint>

// MaskedAttention: B=4, S=1024, WIDTH=1024, H=16, DH=64
// Head-axis softmax. GEMMs: fp16 2-pass split (A=hi+lo, B=rounded) on tensor
// cores (~2.4e-4 accuracy). Scores/attn stored fp16 (halved traffic); av is
// 1-pass (attn exactly fp16). Structure otherwise identical to the proven R3.

#define B_ 4
#define S_ 1024
#define W_ 1024
#define H_ 16
#define DH_ 64
#define M_ (B_ * S_)

// ---------------- device scratch (allocation-free rule) --------------------
__device__ float g_q[M_ * W_];
__device__ float g_k[M_ * W_];
__device__ float g_vt[B_ * H_ * DH_ * S_];            // V transposed [bh][d][s]
__device__ float g_x[M_ * W_];
__device__ uint32_t g_sc[(size_t)B_ * H_ * S_ * S_ / 2];   // scores fp16 (128MB)
__device__ uint32_t g_at[(size_t)B_ * H_ * S_ * S_ / 2];   // attn   fp16 (128MB)

// ---------------- helpers --------------------------------------------------
__device__ __forceinline__ void mma_f16(float* c, const uint32_t* a, const uint32_t* b) {
    asm volatile(
        "mma.sync.aligned.m16n8k16.row.col.f32.f16.f16.f32 "
        "{%0,%1,%2,%3}, {%4,%5,%6,%7}, {%8,%9}, {%0,%1,%2,%3};"
        : "+f"(c[0]), "+f"(c[1]), "+f"(c[2]), "+f"(c[3])
        : "r"(a[0]), "r"(a[1]), "r"(a[2]), "r"(a[3]), "r"(b[0]), "r"(b[1]));
}

// split (x,y) into fp16 hi pair and fp16 lo (residual) pair
__device__ __forceinline__ void split_pack_h(float x, float y, uint32_t& hi, uint32_t& lo) {
    __half hx = __float2half(x);
    __half hy = __float2half(y);
    __half lx = __float2half(x - __half2float(hx));
    __half ly = __float2half(y - __half2float(hy));
    __half2 hp = __halves2half2(hx, hy);
    __half2 lp = __halves2half2(lx, ly);
    hi = *reinterpret_cast<uint32_t*>(&hp);
    lo = *reinterpret_cast<uint32_t*>(&lp);
}

__device__ __forceinline__ uint32_t pack_h2(float x, float y) {
    __half2 p = __halves2half2(__float2half(x), __float2half(y));
    return *reinterpret_cast<uint32_t*>(&p);
}

// ---------------------------------------------------------------------------
// GEMM core: C[m,n] = scale * sum_k A[m,k]*B[n,k] (+bias)
// fp16 split: A = ah + al (2 passes); B rounded to fp16 (1 term).
// 128(M) x BN(N) tile, K-tile 32, 256 threads (8 warps: 4m x 2n).
// NPASS=1 (A already exact fp16, A_HALF) skips the al pass.
// MODE 0: fp32 C. MODE 2: vt fp32 scatter. MODE 3: packed fp16 C.
// ---------------------------------------------------------------------------
template <int BN, int MODE, int NPASS, bool A_HALF>
__device__ __forceinline__ void gemm_core(
        const void* __restrict__ Av, int lda,
        const float* __restrict__ B, int ldb,
        int K, float scale, const float* __restrict__ bias,
        float* __restrict__ Cf, uint32_t* __restrict__ C16,
        int ldc, float* __restrict__ vt) {
    constexpr int NT = BN / 16;
    constexpr int ALSZ = (NPASS == 2) ? 128 * 20 : 4;
    __shared__ uint32_t AsH[128 * 20];
    __shared__ uint32_t AsL[ALSZ];
    __shared__ uint32_t BsH[BN * 20];

    const int tid = threadIdx.x;
    const int lane = tid & 31, warp = tid >> 5;
    const int gid = lane >> 2, tig = lane & 3;
    const int wm = warp >> 1, wn = warp & 1;
    const int m0w = wm * 32, n0w = wn * (BN / 2);
    const int row0 = blockIdx.y * 128;
    const int col0 = blockIdx.x * BN;

    float acc[2][NT][4] = {};

    for (int k0 = 0; k0 < K; k0 += 32) {
        // ---- A tile: 128 rows x 32 k ----
        if (A_HALF) {
            const __half* Ah = (const __half*)Av;
            #pragma unroll
            for (int it = 0; it < 2; it++) {
                int idx = tid + it * 256;          // 512 chunks of 8 halves
                int r = idx >> 2, ck = idx & 3;
                uint4 t = *(const uint4*)&Ah[(size_t)(row0 + r) * lda + k0 + ck * 8];
                *(uint4*)&AsH[r * 20 + ck * 4] = t;
            }
        } else {
            const float* A = (const float*)Av;
            #pragma unroll
            for (int it = 0; it < 4; it++) {
                int idx = tid + it * 256;
                int r = idx >> 3, kv = idx & 7;
                float4 t = *(const float4*)&A[(size_t)(row0 + r) * lda + k0 + kv * 4];
                uint32_t h0, h1, l0, l1;
                split_pack_h(t.x, t.y, h0, l0);
                split_pack_h(t.z, t.w, h1, l1);
                AsH[r * 20 + kv * 2] = h0;  AsH[r * 20 + kv * 2 + 1] = h1;
                if (NPASS == 2) {
                    AsL[r * 20 + kv * 2] = l0;  AsL[r * 20 + kv * 2 + 1] = l1;
                }
            }
        }
        // ---- B tile: BN rows x 32 k (rounded fp16) ----
        #pragma unroll
        for (int it = 0; it < BN / 32; it++) {
            int idx = tid + it * 256;
            int r = idx >> 3, kv = idx & 7;
            float4 t = *(const float4*)&B[(size_t)(col0 + r) * ldb + k0 + kv * 4];
            BsH[r * 20 + kv * 2] = pack_h2(t.x, t.y);
            BsH[r * 20 + kv * 2 + 1] = pack_h2(t.z, t.w);
        }
        __syncthreads();

        #pragma unroll
        for (int ks = 0; ks < 2; ks++) {
            const int kb = ks * 8;
            uint32_t ah[2][4], bh[NT][2];
            #pragma unroll
            for (int mi = 0; mi < 2; mi++) {
                int rb = (m0w + mi * 16 + gid) * 20 + kb;
                ah[mi][0] = AsH[rb + tig];
                ah[mi][1] = AsH[rb + 8 * 20 + tig];
                ah[mi][2] = AsH[rb + tig + 4];
                ah[mi][3] = AsH[rb + 8 * 20 + tig + 4];
            }
            #pragma unroll
            for (int ni = 0; ni < NT; ni++) {
                int rb = (n0w + ni * 8 + gid) * 20 + kb;
                bh[ni][0] = BsH[rb + tig];
                bh[ni][1] = BsH[rb + tig + 4];
            }
            #pragma unroll
            for (int mi = 0; mi < 2; mi++)
                #pragma unroll
                for (int ni = 0; ni < NT; ni++)
                    mma_f16(acc[mi][ni], ah[mi], bh[ni]);
            if (NPASS == 2) {
                uint32_t al[2][4];
                #pragma unroll
                for (int mi = 0; mi < 2; mi++) {
                    int rb = (m0w + mi * 16 + gid) * 20 + kb;
                    al[mi][0] = AsL[rb + tig];
                    al[mi][1] = AsL[rb + 8 * 20 + tig];
                    al[mi][2] = AsL[rb + tig + 4];
                    al[mi][3] = AsL[rb + 8 * 20 + tig + 4];
                }
                #pragma unroll
                for (int mi = 0; mi < 2; mi++)
                    #pragma unroll
                    for (int ni = 0; ni < NT; ni++)
                        mma_f16(acc[mi][ni], al[mi], bh[ni]);
            }
        }
        __syncthreads();
    }

    // ---------------- epilogue ----------------
    #pragma unroll
    for (int mi = 0; mi < 2; mi++) {
        #pragma unroll
        for (int ni = 0; ni < NT; ni++) {
            int row = row0 + m0w + mi * 16 + gid;
            int col = col0 + n0w + ni * 8 + tig * 2;
            float b0 = bias ? bias[col] : 0.0f;
            float b1 = bias ? bias[col + 1] : 0.0f;
            float v0 = acc[mi][ni][0] * scale + b0;
            float v1 = acc[mi][ni][1] * scale + b1;
            float v2 = acc[mi][ni][2] * scale + b0;
            float v3 = acc[mi][ni][3] * scale + b1;
            if (MODE == 0) {
                float2 o0 = {v0, v1}, o1 = {v2, v3};
                *(float2*)&Cf[(size_t)row * ldc + col] = o0;
                *(float2*)&Cf[(size_t)(row + 8) * ldc + col] = o1;
            } else if (MODE == 3) {
                C16[((size_t)row * ldc + col) >> 1] = pack_h2(v0, v1);
                C16[((size_t)(row + 8) * ldc + col) >> 1] = pack_h2(v2, v3);
            } else {
                // vt scatter: row = b*S+s, col = h*64+d -> vt[bh][d][s]
                int b = row >> 10, s = row & 1023;
                int h = col >> 6, d = col & 63;
                size_t base = ((size_t)(b * 16 + h) * 64 + d) * S_;
                vt[base + s] = v0;
                vt[base + S_ + s] = v1;
                vt[base + s + 8] = v2;
                vt[base + S_ + s + 8] = v3;
            }
        }
    }
}

// ---------------- kernel wrappers ------------------------------------------
__global__ __launch_bounds__(256) void proj_kernel(
        const float* __restrict__ A, const float* __restrict__ Wt,
        const float* __restrict__ bias, float* __restrict__ C) {
    gemm_core<128, 0, 2, false>(A, W_, Wt, W_, W_, 1.0f, bias,
                                C, nullptr, W_, nullptr);
}

__global__ __launch_bounds__(256) void proj_vt_kernel(
        const float* __restrict__ A, const float* __restrict__ Wt,
        const float* __restrict__ bias, float* __restrict__ vt) {
    gemm_core<128, 2, 2, false>(A, W_, Wt, W_, W_, 1.0f, bias,
                                nullptr, nullptr, 0, vt);
}

__global__ __launch_bounds__(256) void qk_kernel(
        const float* __restrict__ q, const float* __restrict__ k,
        uint32_t* __restrict__ sc) {
    const int bh = blockIdx.z;
    const int b = bh >> 4, h = bh & 15;
    size_t off = (size_t)b * S_ * W_ + h * DH_;
    gemm_core<128, 3, 2, false>(q + off, W_, k + off, W_, DH_, 0.125f, nullptr,
                                nullptr, sc + (size_t)bh * S_ * S_ / 2, S_,
                                nullptr);
}

__global__ __launch_bounds__(256) void av_kernel(
        const __half* __restrict__ attn, const float* __restrict__ vt,
        float* __restrict__ x) {
    const int bh = blockIdx.z;
    const int b = bh >> 4, h = bh & 15;
    gemm_core<64, 0, 1, true>(attn + (size_t)bh * S_ * S_, S_,
                              vt + (size_t)bh * DH_ * S_, S_,
                              S_, 1.0f, nullptr,
                              x + (size_t)b * S_ * W_ + h * DH_, nullptr, W_,
                              nullptr);
}

__global__ __launch_bounds__(256) void out_kernel(
        const float* __restrict__ A, const float* __restrict__ Wt,
        const float* __restrict__ bias, float* __restrict__ C) {
    gemm_core<128, 0, 2, false>(A, W_, Wt, W_, W_, 1.0f, bias,
                                C, nullptr, W_, nullptr);
}

// ---------------------------------------------------------------------------
// Head-axis softmax: fp16 scores in, fp16 attn out (fp32 math inside).
// Masked (b,q,k): all heads uniform 1/16.
// ---------------------------------------------------------------------------
__global__ __launch_bounds__(256) void head_softmax_kernel(
        const int* __restrict__ mask, const uint32_t* __restrict__ sc,
        uint32_t* __restrict__ at) {
    const int idx = blockIdx.x * blockDim.x + threadIdx.x;   // over B*S*S/4
    const int b = idx >> 18;
    const int qs4 = idx & ((1 << 18) - 1);
    const size_t base = (size_t)b * H_ * S_ * S_ + (size_t)qs4 * 4;  // halves
    const size_t hs = (size_t)S_ * S_;

    int4 mv = ((const int4*)mask)[idx];
    int ms[4] = {mv.x, mv.y, mv.z, mv.w};

    float v[H_][4];
    #pragma unroll
    for (int h = 0; h < H_; h++) {
        uint2 t = *(const uint2*)&sc[(base + h * hs) >> 1];
        __half2 p0 = *reinterpret_cast<__half2*>(&t.x);
        __half2 p1 = *reinterpret_cast<__half2*>(&t.y);
        v[h][0] = __low2float(p0);  v[h][1] = __high2float(p0);
        v[h][2] = __low2float(p1);  v[h][3] = __high2float(p1);
    }

    #pragma unroll
    for (int l = 0; l < 4; l++) {
        if (ms[l] == 0) {
            #pragma unroll
            for (int h = 0; h < H_; h++) v[h][l] = 1.0f / 16.0f;
        } else {
            float mx = v[0][l];
            #pragma unroll
            for (int h = 1; h < H_; h++) mx = fmaxf(mx, v[h][l]);
            float s = 0.0f;
            #pragma unroll
            for (int h = 0; h < H_; h++) {
                v[h][l] = __expf(v[h][l] - mx);
                s += v[h][l];
            }
            float inv = 1.0f / s;
            #pragma unroll
            for (int h = 0; h < H_; h++) v[h][l] *= inv;
        }
    }

    #pragma unroll
    for (int h = 0; h < H_; h++) {
        uint2 t;
        t.x = pack_h2(v[h][0], v[h][1]);
        t.y = pack_h2(v[h][2], v[h][3]);
        *(uint2*)&at[(base + h * hs) >> 1] = t;
    }
}

// ---------------------------------------------------------------------------
extern "C" void kernel_launch(void* const* d_in, const int* in_sizes, int n_in,
                              void* d_out, int out_size) {
    const float* inp  = (const float*)d_in[0];
    const int*   mask = (const int*)  d_in[1];
    const float* wq   = (const float*)d_in[2];
    const float* bq   = (const float*)d_in[3];
    const float* wk   = (const float*)d_in[4];
    const float* bk   = (const float*)d_in[5];
    const float* wv   = (const float*)d_in[6];
    const float* bv   = (const float*)d_in[7];
    const float* wo   = (const float*)d_in[8];
    const float* bo   = (const float*)d_in[9];
    float* out = (float*)d_out;

    #define SYM(p, s) void* p; cudaGetSymbolAddress(&p, s)
    SYM(q, g_q);   SYM(k, g_k);
    SYM(vt, g_vt); SYM(x, g_x);
    SYM(sc, g_sc); SYM(at, g_at);
    #undef SYM

    dim3 pg(W_ / 128, M_ / 128);   // (8, 32)
    // 1) projections (fp32 outputs; v transposed into vt)
    proj_kernel<<<pg, 256>>>(inp, wq, bq, (float*)q);
    proj_kernel<<<pg, 256>>>(inp, wk, bk, (float*)k);
    proj_vt_kernel<<<pg, 256>>>(inp, wv, bv, (float*)vt);

    // 2) QK^T -> fp16 scores (scaled by 1/sqrt(64))
    dim3 qg(S_ / 128, S_ / 128, B_ * H_);   // (8, 8, 64)
    qk_kernel<<<qg, 256>>>((const float*)q, (const float*)k, (uint32_t*)sc);

    // 3) head-axis softmax: fp16 scores -> fp16 attn
    head_softmax_kernel<<<(B_ * S_ * S_ / 4) / 256, 256>>>(
        mask, (const uint32_t*)sc, (uint32_t*)at);

    // 4) attn @ V -> x (1-pass: attn exactly fp16)
    dim3 ag(1, S_ / 128, B_ * H_);   // (1, 8, 64)
    av_kernel<<<ag, 256>>>((const __half*)at, (const float*)vt, (float*)x);

    // 5) output projection
    out_kernel<<<pg, 256>>>((const float*)x, wo, bo, out);
}

// round 12
// speedup vs baseline: 2.4676x; 1.3089x over previous
#include <cuda_runtime.h>
#include <cuda_bf16.h>
#include <cuda_fp16.h>
#include <cstdint>

// MaskedAttention: B=4, S=1024, WIDTH=1024, H=16, DH=64
// Head-axis softmax. GEMMs: fp16 2-pass split (A=hi+lo, B=rounded) on tensor
// cores (~3e-4 accuracy). Scores/attn stored fp16; av is 1-pass.
// __launch_bounds__(256,2) pins 128 regs -> 2 CTAs/SM (the R11 regression fix).

#define B_ 4
#define S_ 1024
#define W_ 1024
#define H_ 16
#define DH_ 64
#define M_ (B_ * S_)

// ---------------- device scratch (allocation-free rule) --------------------
__device__ float g_q[M_ * W_];
__device__ float g_k[M_ * W_];
__device__ float g_vt[B_ * H_ * DH_ * S_];            // V transposed [bh][d][s]
__device__ float g_x[M_ * W_];
__device__ uint32_t g_sc[(size_t)B_ * H_ * S_ * S_ / 2];   // scores fp16 (128MB)
__device__ uint32_t g_at[(size_t)B_ * H_ * S_ * S_ / 2];   // attn   fp16 (128MB)

// ---------------- helpers --------------------------------------------------
__device__ __forceinline__ void mma_f16(float* c, const uint32_t* a, const uint32_t* b) {
    asm volatile(
        "mma.sync.aligned.m16n8k16.row.col.f32.f16.f16.f32 "
        "{%0,%1,%2,%3}, {%4,%5,%6,%7}, {%8,%9}, {%0,%1,%2,%3};"
        : "+f"(c[0]), "+f"(c[1]), "+f"(c[2]), "+f"(c[3])
        : "r"(a[0]), "r"(a[1]), "r"(a[2]), "r"(a[3]), "r"(b[0]), "r"(b[1]));
}

// split (x,y) into fp16 hi pair and fp16 lo (residual) pair
__device__ __forceinline__ void split_pack_h(float x, float y, uint32_t& hi, uint32_t& lo) {
    __half hx = __float2half(x);
    __half hy = __float2half(y);
    __half lx = __float2half(x - __half2float(hx));
    __half ly = __float2half(y - __half2float(hy));
    __half2 hp = __halves2half2(hx, hy);
    __half2 lp = __halves2half2(lx, ly);
    hi = *reinterpret_cast<uint32_t*>(&hp);
    lo = *reinterpret_cast<uint32_t*>(&lp);
}

__device__ __forceinline__ uint32_t pack_h2(float x, float y) {
    __half2 p = __halves2half2(__float2half(x), __float2half(y));
    return *reinterpret_cast<uint32_t*>(&p);
}

// ---------------------------------------------------------------------------
// GEMM core: C[m,n] = scale * sum_k A[m,k]*B[n,k] (+bias)
// fp16 split: A = ah + al (2 passes); B rounded to fp16 (1 term).
// 128(M) x BN(N) tile, K-tile 32, 256 threads (8 warps: 4m x 2n).
// NPASS=1 (A already exact fp16, A_HALF) skips the al pass.
// MODE 0: fp32 C. MODE 2: vt fp32 scatter. MODE 3: packed fp16 C.
// ---------------------------------------------------------------------------
template <int BN, int MODE, int NPASS, bool A_HALF>
__device__ __forceinline__ void gemm_core(
        const void* __restrict__ Av, int lda,
        const float* __restrict__ B, int ldb,
        int K, float scale, const float* __restrict__ bias,
        float* __restrict__ Cf, uint32_t* __restrict__ C16,
        int ldc, float* __restrict__ vt) {
    constexpr int NT = BN / 16;
    constexpr int ALSZ = (NPASS == 2) ? 128 * 20 : 4;
    __shared__ uint32_t AsH[128 * 20];
    __shared__ uint32_t AsL[ALSZ];
    __shared__ uint32_t BsH[BN * 20];

    const int tid = threadIdx.x;
    const int lane = tid & 31, warp = tid >> 5;
    const int gid = lane >> 2, tig = lane & 3;
    const int wm = warp >> 1, wn = warp & 1;
    const int m0w = wm * 32, n0w = wn * (BN / 2);
    const int row0 = blockIdx.y * 128;
    const int col0 = blockIdx.x * BN;

    float acc[2][NT][4] = {};

    for (int k0 = 0; k0 < K; k0 += 32) {
        // ---- A tile: 128 rows x 32 k ----
        if (A_HALF) {
            const __half* Ah = (const __half*)Av;
            #pragma unroll
            for (int it = 0; it < 2; it++) {
                int idx = tid + it * 256;          // 512 chunks of 8 halves
                int r = idx >> 2, ck = idx & 3;
                uint4 t = *(const uint4*)&Ah[(size_t)(row0 + r) * lda + k0 + ck * 8];
                *(uint4*)&AsH[r * 20 + ck * 4] = t;
            }
        } else {
            const float* A = (const float*)Av;
            #pragma unroll
            for (int it = 0; it < 4; it++) {
                int idx = tid + it * 256;
                int r = idx >> 3, kv = idx & 7;
                float4 t = *(const float4*)&A[(size_t)(row0 + r) * lda + k0 + kv * 4];
                uint32_t h0, h1, l0, l1;
                split_pack_h(t.x, t.y, h0, l0);
                split_pack_h(t.z, t.w, h1, l1);
                AsH[r * 20 + kv * 2] = h0;  AsH[r * 20 + kv * 2 + 1] = h1;
                if (NPASS == 2) {
                    AsL[r * 20 + kv * 2] = l0;  AsL[r * 20 + kv * 2 + 1] = l1;
                }
            }
        }
        // ---- B tile: BN rows x 32 k (rounded fp16) ----
        #pragma unroll
        for (int it = 0; it < BN / 32; it++) {
            int idx = tid + it * 256;
            int r = idx >> 3, kv = idx & 7;
            float4 t = *(const float4*)&B[(size_t)(col0 + r) * ldb + k0 + kv * 4];
            BsH[r * 20 + kv * 2] = pack_h2(t.x, t.y);
            BsH[r * 20 + kv * 2 + 1] = pack_h2(t.z, t.w);
        }
        __syncthreads();

        #pragma unroll
        for (int ks = 0; ks < 2; ks++) {
            const int kb = ks * 8;
            uint32_t ah[2][4], bh[NT][2];
            #pragma unroll
            for (int mi = 0; mi < 2; mi++) {
                int rb = (m0w + mi * 16 + gid) * 20 + kb;
                ah[mi][0] = AsH[rb + tig];
                ah[mi][1] = AsH[rb + 8 * 20 + tig];
                ah[mi][2] = AsH[rb + tig + 4];
                ah[mi][3] = AsH[rb + 8 * 20 + tig + 4];
            }
            #pragma unroll
            for (int ni = 0; ni < NT; ni++) {
                int rb = (n0w + ni * 8 + gid) * 20 + kb;
                bh[ni][0] = BsH[rb + tig];
                bh[ni][1] = BsH[rb + tig + 4];
            }
            #pragma unroll
            for (int mi = 0; mi < 2; mi++)
                #pragma unroll
                for (int ni = 0; ni < NT; ni++)
                    mma_f16(acc[mi][ni], ah[mi], bh[ni]);
            if (NPASS == 2) {
                uint32_t al[2][4];
                #pragma unroll
                for (int mi = 0; mi < 2; mi++) {
                    int rb = (m0w + mi * 16 + gid) * 20 + kb;
                    al[mi][0] = AsL[rb + tig];
                    al[mi][1] = AsL[rb + 8 * 20 + tig];
                    al[mi][2] = AsL[rb + tig + 4];
                    al[mi][3] = AsL[rb + 8 * 20 + tig + 4];
                }
                #pragma unroll
                for (int mi = 0; mi < 2; mi++)
                    #pragma unroll
                    for (int ni = 0; ni < NT; ni++)
                        mma_f16(acc[mi][ni], al[mi], bh[ni]);
            }
        }
        __syncthreads();
    }

    // ---------------- epilogue ----------------
    #pragma unroll
    for (int mi = 0; mi < 2; mi++) {
        #pragma unroll
        for (int ni = 0; ni < NT; ni++) {
            int row = row0 + m0w + mi * 16 + gid;
            int col = col0 + n0w + ni * 8 + tig * 2;
            float b0 = bias ? bias[col] : 0.0f;
            float b1 = bias ? bias[col + 1] : 0.0f;
            float v0 = acc[mi][ni][0] * scale + b0;
            float v1 = acc[mi][ni][1] * scale + b1;
            float v2 = acc[mi][ni][2] * scale + b0;
            float v3 = acc[mi][ni][3] * scale + b1;
            if (MODE == 0) {
                float2 o0 = {v0, v1}, o1 = {v2, v3};
                *(float2*)&Cf[(size_t)row * ldc + col] = o0;
                *(float2*)&Cf[(size_t)(row + 8) * ldc + col] = o1;
            } else if (MODE == 3) {
                C16[((size_t)row * ldc + col) >> 1] = pack_h2(v0, v1);
                C16[((size_t)(row + 8) * ldc + col) >> 1] = pack_h2(v2, v3);
            } else {
                // vt scatter: row = b*S+s, col = h*64+d -> vt[bh][d][s]
                int b = row >> 10, s = row & 1023;
                int h = col >> 6, d = col & 63;
                size_t base = ((size_t)(b * 16 + h) * 64 + d) * S_;
                vt[base + s] = v0;
                vt[base + S_ + s] = v1;
                vt[base + s + 8] = v2;
                vt[base + S_ + s + 8] = v3;
            }
        }
    }
}

// ---------------- kernel wrappers (128-reg cap -> 2 CTAs/SM) ----------------
__global__ __launch_bounds__(256, 2) void proj_kernel(
        const float* __restrict__ A, const float* __restrict__ Wt,
        const float* __restrict__ bias, float* __restrict__ C) {
    gemm_core<128, 0, 2, false>(A, W_, Wt, W_, W_, 1.0f, bias,
                                C, nullptr, W_, nullptr);
}

__global__ __launch_bounds__(256, 2) void proj_vt_kernel(
        const float* __restrict__ A, const float* __restrict__ Wt,
        const float* __restrict__ bias, float* __restrict__ vt) {
    gemm_core<128, 2, 2, false>(A, W_, Wt, W_, W_, 1.0f, bias,
                                nullptr, nullptr, 0, vt);
}

__global__ __launch_bounds__(256, 2) void qk_kernel(
        const float* __restrict__ q, const float* __restrict__ k,
        uint32_t* __restrict__ sc) {
    const int bh = blockIdx.z;
    const int b = bh >> 4, h = bh & 15;
    size_t off = (size_t)b * S_ * W_ + h * DH_;
    gemm_core<128, 3, 2, false>(q + off, W_, k + off, W_, DH_, 0.125f, nullptr,
                                nullptr, sc + (size_t)bh * S_ * S_ / 2, S_,
                                nullptr);
}

__global__ __launch_bounds__(256, 2) void av_kernel(
        const __half* __restrict__ attn, const float* __restrict__ vt,
        float* __restrict__ x) {
    const int bh = blockIdx.z;
    const int b = bh >> 4, h = bh & 15;
    gemm_core<64, 0, 1, true>(attn + (size_t)bh * S_ * S_, S_,
                              vt + (size_t)bh * DH_ * S_, S_,
                              S_, 1.0f, nullptr,
                              x + (size_t)b * S_ * W_ + h * DH_, nullptr, W_,
                              nullptr);
}

__global__ __launch_bounds__(256, 2) void out_kernel(
        const float* __restrict__ A, const float* __restrict__ Wt,
        const float* __restrict__ bias, float* __restrict__ C) {
    gemm_core<128, 0, 2, false>(A, W_, Wt, W_, W_, 1.0f, bias,
                                C, nullptr, W_, nullptr);
}

// ---------------------------------------------------------------------------
// Head-axis softmax: fp16 scores in, fp16 attn out (fp32 math inside).
// Masked (b,q,k): all heads uniform 1/16.
// ---------------------------------------------------------------------------
__global__ __launch_bounds__(256) void head_softmax_kernel(
        const int* __restrict__ mask, const uint32_t* __restrict__ sc,
        uint32_t* __restrict__ at) {
    const int idx = blockIdx.x * blockDim.x + threadIdx.x;   // over B*S*S/4
    const int b = idx >> 18;
    const int qs4 = idx & ((1 << 18) - 1);
    const size_t base = (size_t)b * H_ * S_ * S_ + (size_t)qs4 * 4;  // halves
    const size_t hs = (size_t)S_ * S_;

    int4 mv = ((const int4*)mask)[idx];
    int ms[4] = {mv.x, mv.y, mv.z, mv.w};

    float v[H_][4];
    #pragma unroll
    for (int h = 0; h < H_; h++) {
        uint2 t = *(const uint2*)&sc[(base + h * hs) >> 1];
        __half2 p0 = *reinterpret_cast<__half2*>(&t.x);
        __half2 p1 = *reinterpret_cast<__half2*>(&t.y);
        v[h][0] = __low2float(p0);  v[h][1] = __high2float(p0);
        v[h][2] = __low2float(p1);  v[h][3] = __high2float(p1);
    }

    #pragma unroll
    for (int l = 0; l < 4; l++) {
        if (ms[l] == 0) {
            #pragma unroll
            for (int h = 0; h < H_; h++) v[h][l] = 1.0f / 16.0f;
        } else {
            float mx = v[0][l];
            #pragma unroll
            for (int h = 1; h < H_; h++) mx = fmaxf(mx, v[h][l]);
            float s = 0.0f;
            #pragma unroll
            for (int h = 0; h < H_; h++) {
                v[h][l] = __expf(v[h][l] - mx);
                s += v[h][l];
            }
            float inv = 1.0f / s;
            #pragma unroll
            for (int h = 0; h < H_; h++) v[h][l] *= inv;
        }
    }

    #pragma unroll
    for (int h = 0; h < H_; h++) {
        uint2 t;
        t.x = pack_h2(v[h][0], v[h][1]);
        t.y = pack_h2(v[h][2], v[h][3]);
        *(uint2*)&at[(base + h * hs) >> 1] = t;
    }
}

// ---------------------------------------------------------------------------
extern "C" void kernel_launch(void* const* d_in, const int* in_sizes, int n_in,
                              void* d_out, int out_size) {
    const float* inp  = (const float*)d_in[0];
    const int*   mask = (const int*)  d_in[1];
    const float* wq   = (const float*)d_in[2];
    const float* bq   = (const float*)d_in[3];
    const float* wk   = (const float*)d_in[4];
    const float* bk   = (const float*)d_in[5];
    const float* wv   = (const float*)d_in[6];
    const float* bv   = (const float*)d_in[7];
    const float* wo   = (const float*)d_in[8];
    const float* bo   = (const float*)d_in[9];
    float* out = (float*)d_out;

    #define SYM(p, s) void* p; cudaGetSymbolAddress(&p, s)
    SYM(q, g_q);   SYM(k, g_k);
    SYM(vt, g_vt); SYM(x, g_x);
    SYM(sc, g_sc); SYM(at, g_at);
    #undef SYM

    dim3 pg(W_ / 128, M_ / 128);   // (8, 32)
    // 1) projections (fp32 outputs; v transposed into vt)
    proj_kernel<<<pg, 256>>>(inp, wq, bq, (float*)q);
    proj_kernel<<<pg, 256>>>(inp, wk, bk, (float*)k);
    proj_vt_kernel<<<pg, 256>>>(inp, wv, bv, (float*)vt);

    // 2) QK^T -> fp16 scores (scaled by 1/sqrt(64))
    dim3 qg(S_ / 128, S_ / 128, B_ * H_);   // (8, 8, 64)
    qk_kernel<<<qg, 256>>>((const float*)q, (const float*)k, (uint32_t*)sc);

    // 3) head-axis softmax: fp16 scores -> fp16 attn
    head_softmax_kernel<<<(B_ * S_ * S_ / 4) / 256, 256>>>(
        mask, (const uint32_t*)sc, (uint32_t*)at);

    // 4) attn @ V -> x (1-pass: attn exactly fp16)
    dim3 ag(1, S_ / 128, B_ * H_);   // (1, 8, 64)
    av_kernel<<<ag, 256>>>((const __half*)at, (const float*)vt, (float*)x);

    // 5) output projection
    out_kernel<<<pg, 256>>>((const float*)x, wo, bo, out);
}

// round 13
// speedup vs baseline: 2.9193x; 1.1831x over previous
#include <cuda_runtime.h>
#include <cuda_bf16.h>
#include <cuda_fp16.h>
#include <cstdint>

// MaskedAttention: B=4, S=1024, WIDTH=1024, H=16, DH=64
// Head-axis softmax. GEMMs: 1-pass fp16 mma.sync (A and B rounded to fp16,
// fp32 accumulate, ~4.6e-4 total accuracy). Scores/attn stored fp16.
// __launch_bounds__(256,2): 2 CTAs/SM operating point.

#define B_ 4
#define S_ 1024
#define W_ 1024
#define H_ 16
#define DH_ 64
#define M_ (B_ * S_)

// ---------------- device scratch (allocation-free rule) --------------------
__device__ float g_q[M_ * W_];
__device__ float g_k[M_ * W_];
__device__ float g_vt[B_ * H_ * DH_ * S_];            // V transposed [bh][d][s]
__device__ float g_x[M_ * W_];
__device__ uint32_t g_sc[(size_t)B_ * H_ * S_ * S_ / 2];   // scores fp16 (128MB)
__device__ uint32_t g_at[(size_t)B_ * H_ * S_ * S_ / 2];   // attn   fp16 (128MB)

// ---------------- helpers --------------------------------------------------
__device__ __forceinline__ void mma_f16(float* c, const uint32_t* a, const uint32_t* b) {
    asm volatile(
        "mma.sync.aligned.m16n8k16.row.col.f32.f16.f16.f32 "
        "{%0,%1,%2,%3}, {%4,%5,%6,%7}, {%8,%9}, {%0,%1,%2,%3};"
        : "+f"(c[0]), "+f"(c[1]), "+f"(c[2]), "+f"(c[3])
        : "r"(a[0]), "r"(a[1]), "r"(a[2]), "r"(a[3]), "r"(b[0]), "r"(b[1]));
}

__device__ __forceinline__ uint32_t pack_h2(float x, float y) {
    __half2 p = __halves2half2(__float2half(x), __float2half(y));
    return *reinterpret_cast<uint32_t*>(&p);
}

// ---------------------------------------------------------------------------
// GEMM core: C[m,n] = scale * sum_k A[m,k]*B[n,k] (+bias)
// Single-pass fp16 mma (A, B rounded; fp32 accumulate).
// 128(M) x BN(N) tile, K-tile 32, 256 threads (8 warps: 4m x 2n).
// A_HALF: A already fp16 in gmem (av path). MODE 0: fp32 C.
// MODE 2: vt fp32 scatter. MODE 3: packed fp16 C.
// ---------------------------------------------------------------------------
template <int BN, int MODE, bool A_HALF>
__device__ __forceinline__ void gemm_core(
        const void* __restrict__ Av, int lda,
        const float* __restrict__ B, int ldb,
        int K, float scale, const float* __restrict__ bias,
        float* __restrict__ Cf, uint32_t* __restrict__ C16,
        int ldc, float* __restrict__ vt) {
    constexpr int NT = BN / 16;
    __shared__ uint32_t AsH[128 * 20];
    __shared__ uint32_t BsH[BN * 20];

    const int tid = threadIdx.x;
    const int lane = tid & 31, warp = tid >> 5;
    const int gid = lane >> 2, tig = lane & 3;
    const int wm = warp >> 1, wn = warp & 1;
    const int m0w = wm * 32, n0w = wn * (BN / 2);
    const int row0 = blockIdx.y * 128;
    const int col0 = blockIdx.x * BN;

    float acc[2][NT][4] = {};

    for (int k0 = 0; k0 < K; k0 += 32) {
        // ---- A tile: 128 rows x 32 k ----
        if (A_HALF) {
            const __half* Ah = (const __half*)Av;
            #pragma unroll
            for (int it = 0; it < 2; it++) {
                int idx = tid + it * 256;          // 512 chunks of 8 halves
                int r = idx >> 2, ck = idx & 3;
                uint4 t = *(const uint4*)&Ah[(size_t)(row0 + r) * lda + k0 + ck * 8];
                *(uint4*)&AsH[r * 20 + ck * 4] = t;
            }
        } else {
            const float* A = (const float*)Av;
            #pragma unroll
            for (int it = 0; it < 4; it++) {
                int idx = tid + it * 256;
                int r = idx >> 3, kv = idx & 7;
                float4 t = *(const float4*)&A[(size_t)(row0 + r) * lda + k0 + kv * 4];
                AsH[r * 20 + kv * 2] = pack_h2(t.x, t.y);
                AsH[r * 20 + kv * 2 + 1] = pack_h2(t.z, t.w);
            }
        }
        // ---- B tile: BN rows x 32 k (rounded fp16) ----
        #pragma unroll
        for (int it = 0; it < BN / 32; it++) {
            int idx = tid + it * 256;
            int r = idx >> 3, kv = idx & 7;
            float4 t = *(const float4*)&B[(size_t)(col0 + r) * ldb + k0 + kv * 4];
            BsH[r * 20 + kv * 2] = pack_h2(t.x, t.y);
            BsH[r * 20 + kv * 2 + 1] = pack_h2(t.z, t.w);
        }
        __syncthreads();

        #pragma unroll
        for (int ks = 0; ks < 2; ks++) {
            const int kb = ks * 8;
            uint32_t ah[2][4], bh[NT][2];
            #pragma unroll
            for (int mi = 0; mi < 2; mi++) {
                int rb = (m0w + mi * 16 + gid) * 20 + kb;
                ah[mi][0] = AsH[rb + tig];
                ah[mi][1] = AsH[rb + 8 * 20 + tig];
                ah[mi][2] = AsH[rb + tig + 4];
                ah[mi][3] = AsH[rb + 8 * 20 + tig + 4];
            }
            #pragma unroll
            for (int ni = 0; ni < NT; ni++) {
                int rb = (n0w + ni * 8 + gid) * 20 + kb;
                bh[ni][0] = BsH[rb + tig];
                bh[ni][1] = BsH[rb + tig + 4];
            }
            #pragma unroll
            for (int mi = 0; mi < 2; mi++)
                #pragma unroll
                for (int ni = 0; ni < NT; ni++)
                    mma_f16(acc[mi][ni], ah[mi], bh[ni]);
        }
        __syncthreads();
    }

    // ---------------- epilogue ----------------
    #pragma unroll
    for (int mi = 0; mi < 2; mi++) {
        #pragma unroll
        for (int ni = 0; ni < NT; ni++) {
            int row = row0 + m0w + mi * 16 + gid;
            int col = col0 + n0w + ni * 8 + tig * 2;
            float b0 = bias ? bias[col] : 0.0f;
            float b1 = bias ? bias[col + 1] : 0.0f;
            float v0 = acc[mi][ni][0] * scale + b0;
            float v1 = acc[mi][ni][1] * scale + b1;
            float v2 = acc[mi][ni][2] * scale + b0;
            float v3 = acc[mi][ni][3] * scale + b1;
            if (MODE == 0) {
                float2 o0 = {v0, v1}, o1 = {v2, v3};
                *(float2*)&Cf[(size_t)row * ldc + col] = o0;
                *(float2*)&Cf[(size_t)(row + 8) * ldc + col] = o1;
            } else if (MODE == 3) {
                C16[((size_t)row * ldc + col) >> 1] = pack_h2(v0, v1);
                C16[((size_t)(row + 8) * ldc + col) >> 1] = pack_h2(v2, v3);
            } else {
                // vt scatter: row = b*S+s, col = h*64+d -> vt[bh][d][s]
                int b = row >> 10, s = row & 1023;
                int h = col >> 6, d = col & 63;
                size_t base = ((size_t)(b * 16 + h) * 64 + d) * S_;
                vt[base + s] = v0;
                vt[base + S_ + s] = v1;
                vt[base + s + 8] = v2;
                vt[base + S_ + s + 8] = v3;
            }
        }
    }
}

// ---------------- kernel wrappers (2 CTAs/SM) -------------------------------
__global__ __launch_bounds__(256, 2) void proj_kernel(
        const float* __restrict__ A, const float* __restrict__ Wt,
        const float* __restrict__ bias, float* __restrict__ C) {
    gemm_core<128, 0, false>(A, W_, Wt, W_, W_, 1.0f, bias,
                             C, nullptr, W_, nullptr);
}

__global__ __launch_bounds__(256, 2) void proj_vt_kernel(
        const float* __restrict__ A, const float* __restrict__ Wt,
        const float* __restrict__ bias, float* __restrict__ vt) {
    gemm_core<128, 2, false>(A, W_, Wt, W_, W_, 1.0f, bias,
                             nullptr, nullptr, 0, vt);
}

__global__ __launch_bounds__(256, 2) void qk_kernel(
        const float* __restrict__ q, const float* __restrict__ k,
        uint32_t* __restrict__ sc) {
    const int bh = blockIdx.z;
    const int b = bh >> 4, h = bh & 15;
    size_t off = (size_t)b * S_ * W_ + h * DH_;
    gemm_core<128, 3, false>(q + off, W_, k + off, W_, DH_, 0.125f, nullptr,
                             nullptr, sc + (size_t)bh * S_ * S_ / 2, S_,
                             nullptr);
}

__global__ __launch_bounds__(256, 2) void av_kernel(
        const __half* __restrict__ attn, const float* __restrict__ vt,
        float* __restrict__ x) {
    const int bh = blockIdx.z;
    const int b = bh >> 4, h = bh & 15;
    gemm_core<64, 0, true>(attn + (size_t)bh * S_ * S_, S_,
                           vt + (size_t)bh * DH_ * S_, S_,
                           S_, 1.0f, nullptr,
                           x + (size_t)b * S_ * W_ + h * DH_, nullptr, W_,
                           nullptr);
}

__global__ __launch_bounds__(256, 2) void out_kernel(
        const float* __restrict__ A, const float* __restrict__ Wt,
        const float* __restrict__ bias, float* __restrict__ C) {
    gemm_core<128, 0, false>(A, W_, Wt, W_, W_, 1.0f, bias,
                             C, nullptr, W_, nullptr);
}

// ---------------------------------------------------------------------------
// Head-axis softmax: fp16 scores in, fp16 attn out (fp32 math inside).
// Masked (b,q,k): all heads uniform 1/16.
// ---------------------------------------------------------------------------
__global__ __launch_bounds__(256) void head_softmax_kernel(
        const int* __restrict__ mask, const uint32_t* __restrict__ sc,
        uint32_t* __restrict__ at) {
    const int idx = blockIdx.x * blockDim.x + threadIdx.x;   // over B*S*S/4
    const int b = idx >> 18;
    const int qs4 = idx & ((1 << 18) - 1);
    const size_t base = (size_t)b * H_ * S_ * S_ + (size_t)qs4 * 4;  // halves
    const size_t hs = (size_t)S_ * S_;

    int4 mv = ((const int4*)mask)[idx];
    int ms[4] = {mv.x, mv.y, mv.z, mv.w};

    float v[H_][4];
    #pragma unroll
    for (int h = 0; h < H_; h++) {
        uint2 t = *(const uint2*)&sc[(base + h * hs) >> 1];
        __half2 p0 = *reinterpret_cast<__half2*>(&t.x);
        __half2 p1 = *reinterpret_cast<__half2*>(&t.y);
        v[h][0] = __low2float(p0);  v[h][1] = __high2float(p0);
        v[h][2] = __low2float(p1);  v[h][3] = __high2float(p1);
    }

    #pragma unroll
    for (int l = 0; l < 4; l++) {
        if (ms[l] == 0) {
            #pragma unroll
            for (int h = 0; h < H_; h++) v[h][l] = 1.0f / 16.0f;
        } else {
            float mx = v[0][l];
            #pragma unroll
            for (int h = 1; h < H_; h++) mx = fmaxf(mx, v[h][l]);
            float s = 0.0f;
            #pragma unroll
            for (int h = 0; h < H_; h++) {
                v[h][l] = __expf(v[h][l] - mx);
                s += v[h][l];
            }
            float inv = 1.0f / s;
            #pragma unroll
            for (int h = 0; h < H_; h++) v[h][l] *= inv;
        }
    }

    #pragma unroll
    for (int h = 0; h < H_; h++) {
        uint2 t;
        t.x = pack_h2(v[h][0], v[h][1]);
        t.y = pack_h2(v[h][2], v[h][3]);
        *(uint2*)&at[(base + h * hs) >> 1] = t;
    }
}

// ---------------------------------------------------------------------------
extern "C" void kernel_launch(void* const* d_in, const int* in_sizes, int n_in,
                              void* d_out, int out_size) {
    const float* inp  = (const float*)d_in[0];
    const int*   mask = (const int*)  d_in[1];
    const float* wq   = (const float*)d_in[2];
    const float* bq   = (const float*)d_in[3];
    const float* wk   = (const float*)d_in[4];
    const float* bk   = (const float*)d_in[5];
    const float* wv   = (const float*)d_in[6];
    const float* bv   = (const float*)d_in[7];
    const float* wo   = (const float*)d_in[8];
    const float* bo   = (const float*)d_in[9];
    float* out = (float*)d_out;

    #define SYM(p, s) void* p; cudaGetSymbolAddress(&p, s)
    SYM(q, g_q);   SYM(k, g_k);
    SYM(vt, g_vt); SYM(x, g_x);
    SYM(sc, g_sc); SYM(at, g_at);
    #undef SYM

    dim3 pg(W_ / 128, M_ / 128);   // (8, 32)
    // 1) projections (fp32 outputs; v transposed into vt)
    proj_kernel<<<pg, 256>>>(inp, wq, bq, (float*)q);
    proj_kernel<<<pg, 256>>>(inp, wk, bk, (float*)k);
    proj_vt_kernel<<<pg, 256>>>(inp, wv, bv, (float*)vt);

    // 2) QK^T -> fp16 scores (scaled by 1/sqrt(64))
    dim3 qg(S_ / 128, S_ / 128, B_ * H_);   // (8, 8, 64)
    qk_kernel<<<qg, 256>>>((const float*)q, (const float*)k, (uint32_t*)sc);

    // 3) head-axis softmax: fp16 scores -> fp16 attn
    head_softmax_kernel<<<(B_ * S_ * S_ / 4) / 256, 256>>>(
        mask, (const uint32_t*)sc, (uint32_t*)at);

    // 4) attn @ V -> x
    dim3 ag(1, S_ / 128, B_ * H_);   // (1, 8, 64)
    av_kernel<<<ag, 256>>>((const __half*)at, (const float*)vt, (float*)x);

    // 5) output projection
    out_kernel<<<pg, 256>>>((const float*)x, wo, bo, out);
}

// round 14
// speedup vs baseline: 3.0873x; 1.0575x over previous
#include <cuda_runtime.h>
#include <cuda_bf16.h>
#include <cuda_fp16.h>
#include <cstdint>

// MaskedAttention: B=4, S=1024, WIDTH=1024, H=16, DH=64
// Head-axis softmax. GEMMs: 1-pass fp16 mma.sync, fp32 accumulate.
// All intermediate tensors (q, k, vt, x, scores, attn) stored fp16 — the
// rounding is identical to the previous in-loop rounding, so accuracy is
// unchanged (~4.2e-4) while mainloops load pure fp16 (half bytes, no alu).

#define B_ 4
#define S_ 1024
#define W_ 1024
#define H_ 16
#define DH_ 64
#define M_ (B_ * S_)

// ---------------- device scratch (allocation-free rule) --------------------
__device__ __half g_q[M_ * W_];
__device__ __half g_k[M_ * W_];
__device__ __half g_vt[B_ * H_ * DH_ * S_];           // V transposed [bh][d][s]
__device__ __half g_x[M_ * W_];
__device__ uint32_t g_sc[(size_t)B_ * H_ * S_ * S_ / 2];   // scores fp16 (128MB)
__device__ uint32_t g_at[(size_t)B_ * H_ * S_ * S_ / 2];   // attn   fp16 (128MB)

// ---------------- helpers --------------------------------------------------
__device__ __forceinline__ void mma_f16(float* c, const uint32_t* a, const uint32_t* b) {
    asm volatile(
        "mma.sync.aligned.m16n8k16.row.col.f32.f16.f16.f32 "
        "{%0,%1,%2,%3}, {%4,%5,%6,%7}, {%8,%9}, {%0,%1,%2,%3};"
        : "+f"(c[0]), "+f"(c[1]), "+f"(c[2]), "+f"(c[3])
        : "r"(a[0]), "r"(a[1]), "r"(a[2]), "r"(a[3]), "r"(b[0]), "r"(b[1]));
}

__device__ __forceinline__ uint32_t pack_h2(float x, float y) {
    __half2 p = __halves2half2(__float2half(x), __float2half(y));
    return *reinterpret_cast<uint32_t*>(&p);
}

// ---------------------------------------------------------------------------
// GEMM core: C[m,n] = scale * sum_k A[m,k]*B[n,k] (+bias)
// Single-pass fp16 mma (fp32 accumulate).
// 128(M) x BN(N) tile, K-tile 32, 256 threads (8 warps: 4m x 2n).
// A_HALF/B_HALF: operand already fp16 in gmem (uint4 smem fill, no convert).
// MODE 0: fp32 C. MODE 2: vt fp16 scatter. MODE 3: packed fp16 C.
// ---------------------------------------------------------------------------
template <int BN, int MODE, bool A_HALF, bool B_HALF>
__device__ __forceinline__ void gemm_core(
        const void* __restrict__ Av, int lda,
        const void* __restrict__ Bv, int ldb,
        int K, float scale, const float* __restrict__ bias,
        float* __restrict__ Cf, uint32_t* __restrict__ C16,
        int ldc, __half* __restrict__ vt) {
    constexpr int NT = BN / 16;
    __shared__ uint32_t AsH[128 * 20];
    __shared__ uint32_t BsH[BN * 20];

    const int tid = threadIdx.x;
    const int lane = tid & 31, warp = tid >> 5;
    const int gid = lane >> 2, tig = lane & 3;
    const int wm = warp >> 1, wn = warp & 1;
    const int m0w = wm * 32, n0w = wn * (BN / 2);
    const int row0 = blockIdx.y * 128;
    const int col0 = blockIdx.x * BN;

    float acc[2][NT][4] = {};

    for (int k0 = 0; k0 < K; k0 += 32) {
        // ---- A tile: 128 rows x 32 k ----
        if (A_HALF) {
            const __half* Ah = (const __half*)Av;
            #pragma unroll
            for (int it = 0; it < 2; it++) {
                int idx = tid + it * 256;          // 512 chunks of 8 halves
                int r = idx >> 2, ck = idx & 3;
                uint4 t = *(const uint4*)&Ah[(size_t)(row0 + r) * lda + k0 + ck * 8];
                *(uint4*)&AsH[r * 20 + ck * 4] = t;
            }
        } else {
            const float* A = (const float*)Av;
            #pragma unroll
            for (int it = 0; it < 4; it++) {
                int idx = tid + it * 256;
                int r = idx >> 3, kv = idx & 7;
                float4 t = *(const float4*)&A[(size_t)(row0 + r) * lda + k0 + kv * 4];
                AsH[r * 20 + kv * 2] = pack_h2(t.x, t.y);
                AsH[r * 20 + kv * 2 + 1] = pack_h2(t.z, t.w);
            }
        }
        // ---- B tile: BN rows x 32 k ----
        if (B_HALF) {
            const __half* Bh = (const __half*)Bv;
            #pragma unroll
            for (int it = 0; it < BN / 128 + (BN < 128 ? 1 : 0); it++) { }
            #pragma unroll
            for (int it = 0; it < (BN * 4) / 256; it++) {
                int idx = tid + it * 256;          // BN*4 chunks of 8 halves
                int r = idx >> 2, ck = idx & 3;
                uint4 t = *(const uint4*)&Bh[(size_t)(col0 + r) * ldb + k0 + ck * 8];
                *(uint4*)&BsH[r * 20 + ck * 4] = t;
            }
        } else {
            const float* B = (const float*)Bv;
            #pragma unroll
            for (int it = 0; it < BN / 32; it++) {
                int idx = tid + it * 256;
                int r = idx >> 3, kv = idx & 7;
                float4 t = *(const float4*)&B[(size_t)(col0 + r) * ldb + k0 + kv * 4];
                BsH[r * 20 + kv * 2] = pack_h2(t.x, t.y);
                BsH[r * 20 + kv * 2 + 1] = pack_h2(t.z, t.w);
            }
        }
        __syncthreads();

        #pragma unroll
        for (int ks = 0; ks < 2; ks++) {
            const int kb = ks * 8;
            uint32_t ah[2][4], bh[NT][2];
            #pragma unroll
            for (int mi = 0; mi < 2; mi++) {
                int rb = (m0w + mi * 16 + gid) * 20 + kb;
                ah[mi][0] = AsH[rb + tig];
                ah[mi][1] = AsH[rb + 8 * 20 + tig];
                ah[mi][2] = AsH[rb + tig + 4];
                ah[mi][3] = AsH[rb + 8 * 20 + tig + 4];
            }
            #pragma unroll
            for (int ni = 0; ni < NT; ni++) {
                int rb = (n0w + ni * 8 + gid) * 20 + kb;
                bh[ni][0] = BsH[rb + tig];
                bh[ni][1] = BsH[rb + tig + 4];
            }
            #pragma unroll
            for (int mi = 0; mi < 2; mi++)
                #pragma unroll
                for (int ni = 0; ni < NT; ni++)
                    mma_f16(acc[mi][ni], ah[mi], bh[ni]);
        }
        __syncthreads();
    }

    // ---------------- epilogue ----------------
    #pragma unroll
    for (int mi = 0; mi < 2; mi++) {
        #pragma unroll
        for (int ni = 0; ni < NT; ni++) {
            int row = row0 + m0w + mi * 16 + gid;
            int col = col0 + n0w + ni * 8 + tig * 2;
            float b0 = bias ? bias[col] : 0.0f;
            float b1 = bias ? bias[col + 1] : 0.0f;
            float v0 = acc[mi][ni][0] * scale + b0;
            float v1 = acc[mi][ni][1] * scale + b1;
            float v2 = acc[mi][ni][2] * scale + b0;
            float v3 = acc[mi][ni][3] * scale + b1;
            if (MODE == 0) {
                float2 o0 = {v0, v1}, o1 = {v2, v3};
                *(float2*)&Cf[(size_t)row * ldc + col] = o0;
                *(float2*)&Cf[(size_t)(row + 8) * ldc + col] = o1;
            } else if (MODE == 3) {
                C16[((size_t)row * ldc + col) >> 1] = pack_h2(v0, v1);
                C16[((size_t)(row + 8) * ldc + col) >> 1] = pack_h2(v2, v3);
            } else {
                // vt scatter: row = b*S+s, col = h*64+d -> vt[bh][d][s] (fp16)
                int b = row >> 10, s = row & 1023;
                int h = col >> 6, d = col & 63;
                size_t base = ((size_t)(b * 16 + h) * 64 + d) * S_;
                vt[base + s] = __float2half(v0);
                vt[base + S_ + s] = __float2half(v1);
                vt[base + s + 8] = __float2half(v2);
                vt[base + S_ + s + 8] = __float2half(v3);
            }
        }
    }
}

// ---------------- kernel wrappers (2 CTAs/SM) -------------------------------
__global__ __launch_bounds__(256, 2) void proj_kernel(
        const float* __restrict__ A, const float* __restrict__ Wt,
        const float* __restrict__ bias, uint32_t* __restrict__ C16) {
    gemm_core<128, 3, false, false>(A, W_, Wt, W_, W_, 1.0f, bias,
                                    nullptr, C16, W_, nullptr);
}

__global__ __launch_bounds__(256, 2) void proj_vt_kernel(
        const float* __restrict__ A, const float* __restrict__ Wt,
        const float* __restrict__ bias, __half* __restrict__ vt) {
    gemm_core<128, 2, false, false>(A, W_, Wt, W_, W_, 1.0f, bias,
                                    nullptr, nullptr, 0, vt);
}

__global__ __launch_bounds__(256, 2) void qk_kernel(
        const __half* __restrict__ q, const __half* __restrict__ k,
        uint32_t* __restrict__ sc) {
    const int bh = blockIdx.z;
    const int b = bh >> 4, h = bh & 15;
    size_t off = (size_t)b * S_ * W_ + h * DH_;
    gemm_core<128, 3, true, true>(q + off, W_, k + off, W_, DH_, 0.125f,
                                  nullptr, nullptr,
                                  sc + (size_t)bh * S_ * S_ / 2, S_, nullptr);
}

__global__ __launch_bounds__(256, 2) void av_kernel(
        const __half* __restrict__ attn, const __half* __restrict__ vt,
        uint32_t* __restrict__ x16) {
    const int bh = blockIdx.z;
    const int b = bh >> 4, h = bh & 15;
    gemm_core<64, 3, true, true>(attn + (size_t)bh * S_ * S_, S_,
                                 vt + (size_t)bh * DH_ * S_, S_,
                                 S_, 1.0f, nullptr,
                                 nullptr, x16 + (((size_t)b * S_ * W_ + h * DH_) >> 1),
                                 W_, nullptr);
}

__global__ __launch_bounds__(256, 2) void out_kernel(
        const __half* __restrict__ A, const float* __restrict__ Wt,
        const float* __restrict__ bias, float* __restrict__ C) {
    gemm_core<128, 0, true, false>(A, W_, Wt, W_, W_, 1.0f, bias,
                                   C, nullptr, W_, nullptr);
}

// ---------------------------------------------------------------------------
// Head-axis softmax: fp16 scores in, fp16 attn out (fp32 math inside).
// Masked (b,q,k): all heads uniform 1/16.
// ---------------------------------------------------------------------------
__global__ __launch_bounds__(256) void head_softmax_kernel(
        const int* __restrict__ mask, const uint32_t* __restrict__ sc,
        uint32_t* __restrict__ at) {
    const int idx = blockIdx.x * blockDim.x + threadIdx.x;   // over B*S*S/4
    const int b = idx >> 18;
    const int qs4 = idx & ((1 << 18) - 1);
    const size_t base = (size_t)b * H_ * S_ * S_ + (size_t)qs4 * 4;  // halves
    const size_t hs = (size_t)S_ * S_;

    int4 mv = ((const int4*)mask)[idx];
    int ms[4] = {mv.x, mv.y, mv.z, mv.w};

    float v[H_][4];
    #pragma unroll
    for (int h = 0; h < H_; h++) {
        uint2 t = *(const uint2*)&sc[(base + h * hs) >> 1];
        __half2 p0 = *reinterpret_cast<__half2*>(&t.x);
        __half2 p1 = *reinterpret_cast<__half2*>(&t.y);
        v[h][0] = __low2float(p0);  v[h][1] = __high2float(p0);
        v[h][2] = __low2float(p1);  v[h][3] = __high2float(p1);
    }

    #pragma unroll
    for (int l = 0; l < 4; l++) {
        if (ms[l] == 0) {
            #pragma unroll
            for (int h = 0; h < H_; h++) v[h][l] = 1.0f / 16.0f;
        } else {
            float mx = v[0][l];
            #pragma unroll
            for (int h = 1; h < H_; h++) mx = fmaxf(mx, v[h][l]);
            float s = 0.0f;
            #pragma unroll
            for (int h = 0; h < H_; h++) {
                v[h][l] = __expf(v[h][l] - mx);
                s += v[h][l];
            }
            float inv = 1.0f / s;
            #pragma unroll
            for (int h = 0; h < H_; h++) v[h][l] *= inv;
        }
    }

    #pragma unroll
    for (int h = 0; h < H_; h++) {
        uint2 t;
        t.x = pack_h2(v[h][0], v[h][1]);
        t.y = pack_h2(v[h][2], v[h][3]);
        *(uint2*)&at[(base + h * hs) >> 1] = t;
    }
}

// ---------------------------------------------------------------------------
extern "C" void kernel_launch(void* const* d_in, const int* in_sizes, int n_in,
                              void* d_out, int out_size) {
    const float* inp  = (const float*)d_in[0];
    const int*   mask = (const int*)  d_in[1];
    const float* wq   = (const float*)d_in[2];
    const float* bq   = (const float*)d_in[3];
    const float* wk   = (const float*)d_in[4];
    const float* bk   = (const float*)d_in[5];
    const float* wv   = (const float*)d_in[6];
    const float* bv   = (const float*)d_in[7];
    const float* wo   = (const float*)d_in[8];
    const float* bo   = (const float*)d_in[9];
    float* out = (float*)d_out;

    #define SYM(p, s) void* p; cudaGetSymbolAddress(&p, s)
    SYM(q, g_q);   SYM(k, g_k);
    SYM(vt, g_vt); SYM(x, g_x);
    SYM(sc, g_sc); SYM(at, g_at);
    #undef SYM

    dim3 pg(W_ / 128, M_ / 128);   // (8, 32)
    // 1) projections -> fp16 q, k; fp16 transposed vt
    proj_kernel<<<pg, 256>>>(inp, wq, bq, (uint32_t*)q);
    proj_kernel<<<pg, 256>>>(inp, wk, bk, (uint32_t*)k);
    proj_vt_kernel<<<pg, 256>>>(inp, wv, bv, (__half*)vt);

    // 2) QK^T (pure fp16 operands) -> fp16 scores
    dim3 qg(S_ / 128, S_ / 128, B_ * H_);   // (8, 8, 64)
    qk_kernel<<<qg, 256>>>((const __half*)q, (const __half*)k, (uint32_t*)sc);

    // 3) head-axis softmax: fp16 scores -> fp16 attn
    head_softmax_kernel<<<(B_ * S_ * S_ / 4) / 256, 256>>>(
        mask, (const uint32_t*)sc, (uint32_t*)at);

    // 4) attn @ V (pure fp16) -> fp16 x
    dim3 ag(1, S_ / 128, B_ * H_);   // (1, 8, 64)
    av_kernel<<<ag, 256>>>((const __half*)at, (const __half*)vt, (uint32_t*)x);

    // 5) output projection (fp16 A, fp32 W) -> fp32 out
    out_kernel<<<pg, 256>>>((const __half*)x, wo, bo, out);
}

// round 15
// speedup vs baseline: 3.2642x; 1.0573x over previous
#include <cuda_runtime.h>
#include <cuda_bf16.h>
#include <cuda_fp16.h>
#include <cstdint>

// MaskedAttention: B=4, S=1024, WIDTH=1024, H=16, DH=64
// Head-axis softmax. GEMMs: 1-pass fp16 mma.sync, fp32 accumulate,
// ldmatrix.x4 fragment loads (conflict-free on stride-20 rows).
// All intermediates fp16. 2 CTAs/SM operating point.

#define B_ 4
#define S_ 1024
#define W_ 1024
#define H_ 16
#define DH_ 64
#define M_ (B_ * S_)

// ---------------- device scratch (allocation-free rule) --------------------
__device__ __half g_q[M_ * W_];
__device__ __half g_k[M_ * W_];
__device__ __half g_vt[B_ * H_ * DH_ * S_];           // V transposed [bh][d][s]
__device__ __half g_x[M_ * W_];
__device__ uint32_t g_sc[(size_t)B_ * H_ * S_ * S_ / 2];   // scores fp16 (128MB)
__device__ uint32_t g_at[(size_t)B_ * H_ * S_ * S_ / 2];   // attn   fp16 (128MB)

// ---------------- helpers --------------------------------------------------
__device__ __forceinline__ void mma_f16(float* c, const uint32_t* a, const uint32_t* b) {
    asm volatile(
        "mma.sync.aligned.m16n8k16.row.col.f32.f16.f16.f32 "
        "{%0,%1,%2,%3}, {%4,%5,%6,%7}, {%8,%9}, {%0,%1,%2,%3};"
        : "+f"(c[0]), "+f"(c[1]), "+f"(c[2]), "+f"(c[3])
        : "r"(a[0]), "r"(a[1]), "r"(a[2]), "r"(a[3]), "r"(b[0]), "r"(b[1]));
}

__device__ __forceinline__ void ldsm4(uint32_t* r, uint32_t saddr) {
    asm volatile("ldmatrix.sync.aligned.m8n8.x4.shared.b16 {%0,%1,%2,%3}, [%4];"
                 : "=r"(r[0]), "=r"(r[1]), "=r"(r[2]), "=r"(r[3]) : "r"(saddr));
}

__device__ __forceinline__ uint32_t pack_h2(float x, float y) {
    __half2 p = __halves2half2(__float2half(x), __float2half(y));
    return *reinterpret_cast<uint32_t*>(&p);
}

// ---------------------------------------------------------------------------
// GEMM core: C[m,n] = scale * sum_k A[m,k]*B[n,k] (+bias)
// Single-pass fp16 mma (fp32 accumulate); ldmatrix.x4 fragments.
// 128(M) x BN(N) tile, K-tile 32, 256 threads (8 warps: 4m x 2n).
// A_HALF/B_HALF: operand already fp16 in gmem (uint4 smem fill, no convert).
// MODE 0: fp32 C. MODE 2: vt fp16 scatter. MODE 3: packed fp16 C.
// ---------------------------------------------------------------------------
template <int BN, int MODE, bool A_HALF, bool B_HALF>
__device__ __forceinline__ void gemm_core(
        const void* __restrict__ Av, int lda,
        const void* __restrict__ Bv, int ldb,
        int K, float scale, const float* __restrict__ bias,
        float* __restrict__ Cf, uint32_t* __restrict__ C16,
        int ldc, __half* __restrict__ vt) {
    constexpr int NT = BN / 16;
    __shared__ uint32_t AsH[128 * 20];
    __shared__ uint32_t BsH[BN * 20];

    const int tid = threadIdx.x;
    const int lane = tid & 31, warp = tid >> 5;
    const int gid = lane >> 2, tig = lane & 3;
    const int wm = warp >> 1, wn = warp & 1;
    const int m0w = wm * 32, n0w = wn * (BN / 2);
    const int row0 = blockIdx.y * 128;
    const int col0 = blockIdx.x * BN;

    // ldmatrix lane addressing (u32 indices; proven mapping from R4)
    const int a_row = m0w + (lane & 15);
    const int a_co  = (lane >> 4) * 4;
    const int b_row = n0w + ((lane >> 4) & 1) * 8 + (lane & 7);
    const int b_co  = ((lane >> 3) & 1) * 4;
    const uint32_t sA = (uint32_t)__cvta_generic_to_shared(AsH);
    const uint32_t sB = (uint32_t)__cvta_generic_to_shared(BsH);

    float acc[2][NT][4] = {};

    for (int k0 = 0; k0 < K; k0 += 32) {
        // ---- A tile: 128 rows x 32 k ----
        if (A_HALF) {
            const __half* Ah = (const __half*)Av;
            #pragma unroll
            for (int it = 0; it < 2; it++) {
                int idx = tid + it * 256;          // 512 chunks of 8 halves
                int r = idx >> 2, ck = idx & 3;
                uint4 t = *(const uint4*)&Ah[(size_t)(row0 + r) * lda + k0 + ck * 8];
                *(uint4*)&AsH[r * 20 + ck * 4] = t;
            }
        } else {
            const float* A = (const float*)Av;
            #pragma unroll
            for (int it = 0; it < 4; it++) {
                int idx = tid + it * 256;
                int r = idx >> 3, kv = idx & 7;
                float4 t = *(const float4*)&A[(size_t)(row0 + r) * lda + k0 + kv * 4];
                AsH[r * 20 + kv * 2] = pack_h2(t.x, t.y);
                AsH[r * 20 + kv * 2 + 1] = pack_h2(t.z, t.w);
            }
        }
        // ---- B tile: BN rows x 32 k ----
        if (B_HALF) {
            const __half* Bh = (const __half*)Bv;
            #pragma unroll
            for (int it = 0; it < (BN * 4) / 256; it++) {
                int idx = tid + it * 256;          // BN*4 chunks of 8 halves
                int r = idx >> 2, ck = idx & 3;
                uint4 t = *(const uint4*)&Bh[(size_t)(col0 + r) * ldb + k0 + ck * 8];
                *(uint4*)&BsH[r * 20 + ck * 4] = t;
            }
        } else {
            const float* B = (const float*)Bv;
            #pragma unroll
            for (int it = 0; it < BN / 32; it++) {
                int idx = tid + it * 256;
                int r = idx >> 3, kv = idx & 7;
                float4 t = *(const float4*)&B[(size_t)(col0 + r) * ldb + k0 + kv * 4];
                BsH[r * 20 + kv * 2] = pack_h2(t.x, t.y);
                BsH[r * 20 + kv * 2 + 1] = pack_h2(t.z, t.w);
            }
        }
        __syncthreads();

        #pragma unroll
        for (int ks = 0; ks < 2; ks++) {
            const int kb = ks * 8;
            uint32_t ah[2][4], bh[NT][2];
            #pragma unroll
            for (int mi = 0; mi < 2; mi++)
                ldsm4(ah[mi], sA + (uint32_t)((a_row + mi * 16) * 20 + kb + a_co) * 4);
            #pragma unroll
            for (int np = 0; np < NT / 2; np++) {
                uint32_t r[4];
                ldsm4(r, sB + (uint32_t)((b_row + np * 16) * 20 + kb + b_co) * 4);
                bh[np * 2][0] = r[0];     bh[np * 2][1] = r[1];
                bh[np * 2 + 1][0] = r[2]; bh[np * 2 + 1][1] = r[3];
            }
            #pragma unroll
            for (int mi = 0; mi < 2; mi++)
                #pragma unroll
                for (int ni = 0; ni < NT; ni++)
                    mma_f16(acc[mi][ni], ah[mi], bh[ni]);
        }
        __syncthreads();
    }

    // ---------------- epilogue ----------------
    #pragma unroll
    for (int mi = 0; mi < 2; mi++) {
        #pragma unroll
        for (int ni = 0; ni < NT; ni++) {
            int row = row0 + m0w + mi * 16 + gid;
            int col = col0 + n0w + ni * 8 + tig * 2;
            float b0 = bias ? bias[col] : 0.0f;
            float b1 = bias ? bias[col + 1] : 0.0f;
            float v0 = acc[mi][ni][0] * scale + b0;
            float v1 = acc[mi][ni][1] * scale + b1;
            float v2 = acc[mi][ni][2] * scale + b0;
            float v3 = acc[mi][ni][3] * scale + b1;
            if (MODE == 0) {
                float2 o0 = {v0, v1}, o1 = {v2, v3};
                *(float2*)&Cf[(size_t)row * ldc + col] = o0;
                *(float2*)&Cf[(size_t)(row + 8) * ldc + col] = o1;
            } else if (MODE == 3) {
                C16[((size_t)row * ldc + col) >> 1] = pack_h2(v0, v1);
                C16[((size_t)(row + 8) * ldc + col) >> 1] = pack_h2(v2, v3);
            } else {
                // vt scatter: row = b*S+s, col = h*64+d -> vt[bh][d][s] (fp16)
                int b = row >> 10, s = row & 1023;
                int h = col >> 6, d = col & 63;
                size_t base = ((size_t)(b * 16 + h) * 64 + d) * S_;
                vt[base + s] = __float2half(v0);
                vt[base + S_ + s] = __float2half(v1);
                vt[base + s + 8] = __float2half(v2);
                vt[base + S_ + s + 8] = __float2half(v3);
            }
        }
    }
}

// ---------------- kernel wrappers (2 CTAs/SM) -------------------------------
__global__ __launch_bounds__(256, 2) void proj_kernel(
        const float* __restrict__ A, const float* __restrict__ Wt,
        const float* __restrict__ bias, uint32_t* __restrict__ C16) {
    gemm_core<128, 3, false, false>(A, W_, Wt, W_, W_, 1.0f, bias,
                                    nullptr, C16, W_, nullptr);
}

__global__ __launch_bounds__(256, 2) void proj_vt_kernel(
        const float* __restrict__ A, const float* __restrict__ Wt,
        const float* __restrict__ bias, __half* __restrict__ vt) {
    gemm_core<128, 2, false, false>(A, W_, Wt, W_, W_, 1.0f, bias,
                                    nullptr, nullptr, 0, vt);
}

__global__ __launch_bounds__(256, 2) void qk_kernel(
        const __half* __restrict__ q, const __half* __restrict__ k,
        uint32_t* __restrict__ sc) {
    const int bh = blockIdx.z;
    const int b = bh >> 4, h = bh & 15;
    size_t off = (size_t)b * S_ * W_ + h * DH_;
    gemm_core<128, 3, true, true>(q + off, W_, k + off, W_, DH_, 0.125f,
                                  nullptr, nullptr,
                                  sc + (size_t)bh * S_ * S_ / 2, S_, nullptr);
}

__global__ __launch_bounds__(256, 2) void av_kernel(
        const __half* __restrict__ attn, const __half* __restrict__ vt,
        uint32_t* __restrict__ x16) {
    const int bh = blockIdx.z;
    const int b = bh >> 4, h = bh & 15;
    gemm_core<64, 3, true, true>(attn + (size_t)bh * S_ * S_, S_,
                                 vt + (size_t)bh * DH_ * S_, S_,
                                 S_, 1.0f, nullptr,
                                 nullptr, x16 + (((size_t)b * S_ * W_ + h * DH_) >> 1),
                                 W_, nullptr);
}

__global__ __launch_bounds__(256, 2) void out_kernel(
        const __half* __restrict__ A, const float* __restrict__ Wt,
        const float* __restrict__ bias, float* __restrict__ C) {
    gemm_core<128, 0, true, false>(A, W_, Wt, W_, W_, 1.0f, bias,
                                   C, nullptr, W_, nullptr);
}

// ---------------------------------------------------------------------------
// Head-axis softmax: fp16 scores in, fp16 attn out (fp32 math inside).
// Masked (b,q,k): all heads uniform 1/16.
// ---------------------------------------------------------------------------
__global__ __launch_bounds__(256) void head_softmax_kernel(
        const int* __restrict__ mask, const uint32_t* __restrict__ sc,
        uint32_t* __restrict__ at) {
    const int idx = blockIdx.x * blockDim.x + threadIdx.x;   // over B*S*S/4
    const int b = idx >> 18;
    const int qs4 = idx & ((1 << 18) - 1);
    const size_t base = (size_t)b * H_ * S_ * S_ + (size_t)qs4 * 4;  // halves
    const size_t hs = (size_t)S_ * S_;

    int4 mv = ((const int4*)mask)[idx];
    int ms[4] = {mv.x, mv.y, mv.z, mv.w};

    float v[H_][4];
    #pragma unroll
    for (int h = 0; h < H_; h++) {
        uint2 t = *(const uint2*)&sc[(base + h * hs) >> 1];
        __half2 p0 = *reinterpret_cast<__half2*>(&t.x);
        __half2 p1 = *reinterpret_cast<__half2*>(&t.y);
        v[h][0] = __low2float(p0);  v[h][1] = __high2float(p0);
        v[h][2] = __low2float(p1);  v[h][3] = __high2float(p1);
    }

    #pragma unroll
    for (int l = 0; l < 4; l++) {
        if (ms[l] == 0) {
            #pragma unroll
            for (int h = 0; h < H_; h++) v[h][l] = 1.0f / 16.0f;
        } else {
            float mx = v[0][l];
            #pragma unroll
            for (int h = 1; h < H_; h++) mx = fmaxf(mx, v[h][l]);
            float s = 0.0f;
            #pragma unroll
            for (int h = 0; h < H_; h++) {
                v[h][l] = __expf(v[h][l] - mx);
                s += v[h][l];
            }
            float inv = 1.0f / s;
            #pragma unroll
            for (int h = 0; h < H_; h++) v[h][l] *= inv;
        }
    }

    #pragma unroll
    for (int h = 0; h < H_; h++) {
        uint2 t;
        t.x = pack_h2(v[h][0], v[h][1]);
        t.y = pack_h2(v[h][2], v[h][3]);
        *(uint2*)&at[(base + h * hs) >> 1] = t;
    }
}

// ---------------------------------------------------------------------------
extern "C" void kernel_launch(void* const* d_in, const int* in_sizes, int n_in,
                              void* d_out, int out_size) {
    const float* inp  = (const float*)d_in[0];
    const int*   mask = (const int*)  d_in[1];
    const float* wq   = (const float*)d_in[2];
    const float* bq   = (const float*)d_in[3];
    const float* wk   = (const float*)d_in[4];
    const float* bk   = (const float*)d_in[5];
    const float* wv   = (const float*)d_in[6];
    const float* bv   = (const float*)d_in[7];
    const float* wo   = (const float*)d_in[8];
    const float* bo   = (const float*)d_in[9];
    float* out = (float*)d_out;

    #define SYM(p, s) void* p; cudaGetSymbolAddress(&p, s)
    SYM(q, g_q);   SYM(k, g_k);
    SYM(vt, g_vt); SYM(x, g_x);
    SYM(sc, g_sc); SYM(at, g_at);
    #undef SYM

    dim3 pg(W_ / 128, M_ / 128);   // (8, 32)
    // 1) projections -> fp16 q, k; fp16 transposed vt
    proj_kernel<<<pg, 256>>>(inp, wq, bq, (uint32_t*)q);
    proj_kernel<<<pg, 256>>>(inp, wk, bk, (uint32_t*)k);
    proj_vt_kernel<<<pg, 256>>>(inp, wv, bv, (__half*)vt);

    // 2) QK^T (pure fp16 operands) -> fp16 scores
    dim3 qg(S_ / 128, S_ / 128, B_ * H_);   // (8, 8, 64)
    qk_kernel<<<qg, 256>>>((const __half*)q, (const __half*)k, (uint32_t*)sc);

    // 3) head-axis softmax: fp16 scores -> fp16 attn
    head_softmax_kernel<<<(B_ * S_ * S_ / 4) / 256, 256>>>(
        mask, (const uint32_t*)sc, (uint32_t*)at);

    // 4) attn @ V (pure fp16) -> fp16 x
    dim3 ag(1, S_ / 128, B_ * H_);   // (1, 8, 64)
    av_kernel<<<ag, 256>>>((const __half*)at, (const __half*)vt, (uint32_t*)x);

    // 5) output projection (fp16 A, fp32 W) -> fp32 out
    out_kernel<<<pg, 256>>>((const __half*)x, wo, bo, out);
}

// round 16
// speedup vs baseline: 3.4000x; 1.0416x over previous
#include <cuda_runtime.h>
#include <cuda_bf16.h>
#include <cuda_fp16.h>
#include <cstdint>

// MaskedAttention: B=4, S=1024, WIDTH=1024, H=16, DH=64
// Head-axis softmax. GEMMs: 1-pass fp16 mma.sync, fp32 accumulate, ldmatrix.x4.
// qk: persistent-A restructure (K=64 -> A fragments live in registers across
// 4 K-column tiles; single shared smem buffer). Projections merged (gridz=3).

#define B_ 4
#define S_ 1024
#define W_ 1024
#define H_ 16
#define DH_ 64
#define M_ (B_ * S_)

// ---------------- device scratch (allocation-free rule) --------------------
__device__ __half g_q[M_ * W_];
__device__ __half g_k[M_ * W_];
__device__ __half g_vt[B_ * H_ * DH_ * S_];           // V transposed [bh][d][s]
__device__ __half g_x[M_ * W_];
__device__ uint32_t g_sc[(size_t)B_ * H_ * S_ * S_ / 2];   // scores fp16 (128MB)
__device__ uint32_t g_at[(size_t)B_ * H_ * S_ * S_ / 2];   // attn   fp16 (128MB)

// ---------------- helpers --------------------------------------------------
__device__ __forceinline__ void mma_f16(float* c, const uint32_t* a, const uint32_t* b) {
    asm volatile(
        "mma.sync.aligned.m16n8k16.row.col.f32.f16.f16.f32 "
        "{%0,%1,%2,%3}, {%4,%5,%6,%7}, {%8,%9}, {%0,%1,%2,%3};"
        : "+f"(c[0]), "+f"(c[1]), "+f"(c[2]), "+f"(c[3])
        : "r"(a[0]), "r"(a[1]), "r"(a[2]), "r"(a[3]), "r"(b[0]), "r"(b[1]));
}

__device__ __forceinline__ void ldsm4(uint32_t* r, uint32_t saddr) {
    asm volatile("ldmatrix.sync.aligned.m8n8.x4.shared.b16 {%0,%1,%2,%3}, [%4];"
                 : "=r"(r[0]), "=r"(r[1]), "=r"(r[2]), "=r"(r[3]) : "r"(saddr));
}

__device__ __forceinline__ uint32_t pack_h2(float x, float y) {
    __half2 p = __halves2half2(__float2half(x), __float2half(y));
    return *reinterpret_cast<uint32_t*>(&p);
}

// ---------------------------------------------------------------------------
// Generic GEMM core (proven R15): C[m,n] = scale * sum_k A[m,k]*B[n,k] (+bias)
// 1-pass fp16 mma; ldmatrix.x4; 128(M) x BN(N) tile, K-tile 32, 256 threads.
// MODE 0: fp32 C. MODE 3: packed fp16 C. MODE 4: runtime (vt? scatter : fp16 C).
// ---------------------------------------------------------------------------
template <int BN, int MODE, bool A_HALF, bool B_HALF>
__device__ __forceinline__ void gemm_core(
        const void* __restrict__ Av, int lda,
        const void* __restrict__ Bv, int ldb,
        int K, float scale, const float* __restrict__ bias,
        float* __restrict__ Cf, uint32_t* __restrict__ C16,
        int ldc, __half* __restrict__ vt) {
    constexpr int NT = BN / 16;
    __shared__ uint32_t AsH[128 * 20];
    __shared__ uint32_t BsH[BN * 20];

    const int tid = threadIdx.x;
    const int lane = tid & 31, warp = tid >> 5;
    const int gid = lane >> 2, tig = lane & 3;
    const int wm = warp >> 1, wn = warp & 1;
    const int m0w = wm * 32, n0w = wn * (BN / 2);
    const int row0 = blockIdx.y * 128;
    const int col0 = blockIdx.x * BN;

    const int a_row = m0w + (lane & 15);
    const int a_co  = (lane >> 4) * 4;
    const int b_row = n0w + ((lane >> 4) & 1) * 8 + (lane & 7);
    const int b_co  = ((lane >> 3) & 1) * 4;
    const uint32_t sA = (uint32_t)__cvta_generic_to_shared(AsH);
    const uint32_t sB = (uint32_t)__cvta_generic_to_shared(BsH);

    float acc[2][NT][4] = {};

    for (int k0 = 0; k0 < K; k0 += 32) {
        if (A_HALF) {
            const __half* Ah = (const __half*)Av;
            #pragma unroll
            for (int it = 0; it < 2; it++) {
                int idx = tid + it * 256;
                int r = idx >> 2, ck = idx & 3;
                uint4 t = *(const uint4*)&Ah[(size_t)(row0 + r) * lda + k0 + ck * 8];
                *(uint4*)&AsH[r * 20 + ck * 4] = t;
            }
        } else {
            const float* A = (const float*)Av;
            #pragma unroll
            for (int it = 0; it < 4; it++) {
                int idx = tid + it * 256;
                int r = idx >> 3, kv = idx & 7;
                float4 t = *(const float4*)&A[(size_t)(row0 + r) * lda + k0 + kv * 4];
                AsH[r * 20 + kv * 2] = pack_h2(t.x, t.y);
                AsH[r * 20 + kv * 2 + 1] = pack_h2(t.z, t.w);
            }
        }
        if (B_HALF) {
            const __half* Bh = (const __half*)Bv;
            #pragma unroll
            for (int it = 0; it < (BN * 4) / 256; it++) {
                int idx = tid + it * 256;
                int r = idx >> 2, ck = idx & 3;
                uint4 t = *(const uint4*)&Bh[(size_t)(col0 + r) * ldb + k0 + ck * 8];
                *(uint4*)&BsH[r * 20 + ck * 4] = t;
            }
        } else {
            const float* B = (const float*)Bv;
            #pragma unroll
            for (int it = 0; it < BN / 32; it++) {
                int idx = tid + it * 256;
                int r = idx >> 3, kv = idx & 7;
                float4 t = *(const float4*)&B[(size_t)(col0 + r) * ldb + k0 + kv * 4];
                BsH[r * 20 + kv * 2] = pack_h2(t.x, t.y);
                BsH[r * 20 + kv * 2 + 1] = pack_h2(t.z, t.w);
            }
        }
        __syncthreads();

        #pragma unroll
        for (int ks = 0; ks < 2; ks++) {
            const int kb = ks * 8;
            uint32_t ah[2][4], bh[NT][2];
            #pragma unroll
            for (int mi = 0; mi < 2; mi++)
                ldsm4(ah[mi], sA + (uint32_t)((a_row + mi * 16) * 20 + kb + a_co) * 4);
            #pragma unroll
            for (int np = 0; np < NT / 2; np++) {
                uint32_t r[4];
                ldsm4(r, sB + (uint32_t)((b_row + np * 16) * 20 + kb + b_co) * 4);
                bh[np * 2][0] = r[0];     bh[np * 2][1] = r[1];
                bh[np * 2 + 1][0] = r[2]; bh[np * 2 + 1][1] = r[3];
            }
            #pragma unroll
            for (int mi = 0; mi < 2; mi++)
                #pragma unroll
                for (int ni = 0; ni < NT; ni++)
                    mma_f16(acc[mi][ni], ah[mi], bh[ni]);
        }
        __syncthreads();
    }

    #pragma unroll
    for (int mi = 0; mi < 2; mi++) {
        #pragma unroll
        for (int ni = 0; ni < NT; ni++) {
            int row = row0 + m0w + mi * 16 + gid;
            int col = col0 + n0w + ni * 8 + tig * 2;
            float b0 = bias ? bias[col] : 0.0f;
            float b1 = bias ? bias[col + 1] : 0.0f;
            float v0 = acc[mi][ni][0] * scale + b0;
            float v1 = acc[mi][ni][1] * scale + b1;
            float v2 = acc[mi][ni][2] * scale + b0;
            float v3 = acc[mi][ni][3] * scale + b1;
            if (MODE == 0) {
                float2 o0 = {v0, v1}, o1 = {v2, v3};
                *(float2*)&Cf[(size_t)row * ldc + col] = o0;
                *(float2*)&Cf[(size_t)(row + 8) * ldc + col] = o1;
            } else if (MODE == 3) {
                C16[((size_t)row * ldc + col) >> 1] = pack_h2(v0, v1);
                C16[((size_t)(row + 8) * ldc + col) >> 1] = pack_h2(v2, v3);
            } else {   // MODE 4: runtime select
                if (vt) {
                    int b = row >> 10, s = row & 1023;
                    int h = col >> 6, d = col & 63;
                    size_t base = ((size_t)(b * 16 + h) * 64 + d) * S_;
                    vt[base + s] = __float2half(v0);
                    vt[base + S_ + s] = __float2half(v1);
                    vt[base + s + 8] = __float2half(v2);
                    vt[base + S_ + s + 8] = __float2half(v3);
                } else {
                    C16[((size_t)row * ldc + col) >> 1] = pack_h2(v0, v1);
                    C16[((size_t)(row + 8) * ldc + col) >> 1] = pack_h2(v2, v3);
                }
            }
        }
    }
}

// ---------------------------------------------------------------------------
// qk: persistent-A kernel. K = DH = 64. Block owns 128 q-rows x 512 k-cols
// (4 column tiles of 128). A fragments hoisted to registers once; one shared
// smem buffer (Q first, then reused for K tiles). Accumulation order over K
// identical to the generic core -> bit-identical scores.
// ---------------------------------------------------------------------------
__global__ __launch_bounds__(256, 2) void qk_kernel(
        const __half* __restrict__ q, const __half* __restrict__ k,
        uint32_t* __restrict__ sc) {
    constexpr int RS = 36;               // u32 row stride (32 data + 4 pad)
    __shared__ uint32_t Ts[128 * RS];    // 18.4 KB, Q then K tiles

    const int tid = threadIdx.x;
    const int lane = tid & 31, warp = tid >> 5;
    const int gid = lane >> 2, tig = lane & 3;
    const int wm = warp >> 1, wn = warp & 1;
    const int m0w = wm * 32, n0w = wn * 64;
    const int bh = blockIdx.z;
    const int b = bh >> 4, h = bh & 15;
    const int row0 = blockIdx.y * 128;
    const int colbase = blockIdx.x * 512;

    const __half* qb = q + (size_t)b * S_ * W_ + h * DH_;
    const __half* kb = k + (size_t)b * S_ * W_ + h * DH_;
    uint32_t* scb = sc + (size_t)bh * S_ * S_ / 2;

    const int a_row = m0w + (lane & 15);
    const int a_co  = (lane >> 4) * 4;
    const int b_row = n0w + ((lane >> 4) & 1) * 8 + (lane & 7);
    const int b_co  = ((lane >> 3) & 1) * 4;
    const uint32_t sT = (uint32_t)__cvta_generic_to_shared(Ts);

    // ---- load Q tile (128 x 64 halves) once ----
    #pragma unroll
    for (int it = 0; it < 4; it++) {
        int c = tid + it * 256;                  // 1024 uint4 chunks
        int r = c >> 3, ck = c & 7;
        uint4 t = *(const uint4*)&qb[(size_t)(row0 + r) * W_ + ck * 8];
        *(uint4*)&Ts[r * RS + ck * 4] = t;
    }
    __syncthreads();

    // ---- hoist A fragments for the whole K=64 reduction ----
    uint32_t ah[2][4][4];
    #pragma unroll
    for (int mi = 0; mi < 2; mi++)
        #pragma unroll
        for (int ks = 0; ks < 4; ks++)
            ldsm4(ah[mi][ks], sT + (uint32_t)((a_row + mi * 16) * RS + ks * 8 + a_co) * 4);

    // ---- loop over 4 K-column tiles, reusing the smem buffer ----
    #pragma unroll 1
    for (int cb = 0; cb < 4; cb++) {
        const int col0 = colbase + cb * 128;
        __syncthreads();                         // prior reads done before overwrite
        #pragma unroll
        for (int it = 0; it < 4; it++) {
            int c = tid + it * 256;
            int r = c >> 3, ck = c & 7;
            uint4 t = *(const uint4*)&kb[(size_t)(col0 + r) * W_ + ck * 8];
            *(uint4*)&Ts[r * RS + ck * 4] = t;
        }
        __syncthreads();

        float acc[2][8][4] = {};
        #pragma unroll
        for (int ks = 0; ks < 4; ks++) {
            #pragma unroll
            for (int np = 0; np < 4; np++) {
                uint32_t r[4];
                ldsm4(r, sT + (uint32_t)((b_row + np * 16) * RS + ks * 8 + b_co) * 4);
                uint32_t b0[2] = {r[0], r[1]};
                uint32_t b1[2] = {r[2], r[3]};
                #pragma unroll
                for (int mi = 0; mi < 2; mi++) {
                    mma_f16(acc[mi][np * 2], ah[mi][ks], b0);
                    mma_f16(acc[mi][np * 2 + 1], ah[mi][ks], b1);
                }
            }
        }

        // epilogue: fp16 scores * 0.125
        #pragma unroll
        for (int mi = 0; mi < 2; mi++) {
            #pragma unroll
            for (int ni = 0; ni < 8; ni++) {
                int row = row0 + m0w + mi * 16 + gid;
                int col = col0 + n0w + ni * 8 + tig * 2;
                scb[((size_t)row * S_ + col) >> 1] =
                    pack_h2(acc[mi][ni][0] * 0.125f, acc[mi][ni][1] * 0.125f);
                scb[((size_t)(row + 8) * S_ + col) >> 1] =
                    pack_h2(acc[mi][ni][2] * 0.125f, acc[mi][ni][3] * 0.125f);
            }
        }
    }
}

// ---------------- kernel wrappers (2 CTAs/SM) -------------------------------
// merged q/k/v projections: blockIdx.z selects weight/bias/output
__global__ __launch_bounds__(256, 2) void proj_qkv_kernel(
        const float* __restrict__ inp,
        const float* __restrict__ wq, const float* __restrict__ bq,
        const float* __restrict__ wk, const float* __restrict__ bk,
        const float* __restrict__ wv, const float* __restrict__ bv,
        uint32_t* __restrict__ q16, uint32_t* __restrict__ k16,
        __half* __restrict__ vtp) {
    const float* Wt; const float* bias;
    uint32_t* C16 = nullptr; __half* vt = nullptr;
    if (blockIdx.z == 0)      { Wt = wq; bias = bq; C16 = q16; }
    else if (blockIdx.z == 1) { Wt = wk; bias = bk; C16 = k16; }
    else                      { Wt = wv; bias = bv; vt = vtp; }
    gemm_core<128, 4, false, false>(inp, W_, Wt, W_, W_, 1.0f, bias,
                                    nullptr, C16, W_, vt);
}

__global__ __launch_bounds__(256, 2) void av_kernel(
        const __half* __restrict__ attn, const __half* __restrict__ vt,
        uint32_t* __restrict__ x16) {
    const int bh = blockIdx.z;
    const int b = bh >> 4, h = bh & 15;
    gemm_core<64, 3, true, true>(attn + (size_t)bh * S_ * S_, S_,
                                 vt + (size_t)bh * DH_ * S_, S_,
                                 S_, 1.0f, nullptr,
                                 nullptr, x16 + (((size_t)b * S_ * W_ + h * DH_) >> 1),
                                 W_, nullptr);
}

__global__ __launch_bounds__(256, 2) void out_kernel(
        const __half* __restrict__ A, const float* __restrict__ Wt,
        const float* __restrict__ bias, float* __restrict__ C) {
    gemm_core<128, 0, true, false>(A, W_, Wt, W_, W_, 1.0f, bias,
                                   C, nullptr, W_, nullptr);
}

// ---------------------------------------------------------------------------
// Head-axis softmax: fp16 scores in, fp16 attn out (fp32 math inside).
// ---------------------------------------------------------------------------
__global__ __launch_bounds__(256) void head_softmax_kernel(
        const int* __restrict__ mask, const uint32_t* __restrict__ sc,
        uint32_t* __restrict__ at) {
    const int idx = blockIdx.x * blockDim.x + threadIdx.x;   // over B*S*S/4
    const int b = idx >> 18;
    const int qs4 = idx & ((1 << 18) - 1);
    const size_t base = (size_t)b * H_ * S_ * S_ + (size_t)qs4 * 4;  // halves
    const size_t hs = (size_t)S_ * S_;

    int4 mv = ((const int4*)mask)[idx];
    int ms[4] = {mv.x, mv.y, mv.z, mv.w};

    float v[H_][4];
    #pragma unroll
    for (int h = 0; h < H_; h++) {
        uint2 t = *(const uint2*)&sc[(base + h * hs) >> 1];
        __half2 p0 = *reinterpret_cast<__half2*>(&t.x);
        __half2 p1 = *reinterpret_cast<__half2*>(&t.y);
        v[h][0] = __low2float(p0);  v[h][1] = __high2float(p0);
        v[h][2] = __low2float(p1);  v[h][3] = __high2float(p1);
    }

    #pragma unroll
    for (int l = 0; l < 4; l++) {
        if (ms[l] == 0) {
            #pragma unroll
            for (int h = 0; h < H_; h++) v[h][l] = 1.0f / 16.0f;
        } else {
            float mx = v[0][l];
            #pragma unroll
            for (int h = 1; h < H_; h++) mx = fmaxf(mx, v[h][l]);
            float s = 0.0f;
            #pragma unroll
            for (int h = 0; h < H_; h++) {
                v[h][l] = __expf(v[h][l] - mx);
                s += v[h][l];
            }
            float inv = 1.0f / s;
            #pragma unroll
            for (int h = 0; h < H_; h++) v[h][l] *= inv;
        }
    }

    #pragma unroll
    for (int h = 0; h < H_; h++) {
        uint2 t;
        t.x = pack_h2(v[h][0], v[h][1]);
        t.y = pack_h2(v[h][2], v[h][3]);
        *(uint2*)&at[(base + h * hs) >> 1] = t;
    }
}

// ---------------------------------------------------------------------------
extern "C" void kernel_launch(void* const* d_in, const int* in_sizes, int n_in,
                              void* d_out, int out_size) {
    const float* inp  = (const float*)d_in[0];
    const int*   mask = (const int*)  d_in[1];
    const float* wq   = (const float*)d_in[2];
    const float* bq   = (const float*)d_in[3];
    const float* wk   = (const float*)d_in[4];
    const float* bk   = (const float*)d_in[5];
    const float* wv   = (const float*)d_in[6];
    const float* bv   = (const float*)d_in[7];
    const float* wo   = (const float*)d_in[8];
    const float* bo   = (const float*)d_in[9];
    float* out = (float*)d_out;

    #define SYM(p, s) void* p; cudaGetSymbolAddress(&p, s)
    SYM(q, g_q);   SYM(k, g_k);
    SYM(vt, g_vt); SYM(x, g_x);
    SYM(sc, g_sc); SYM(at, g_at);
    #undef SYM

    // 1) merged projections -> fp16 q, k; fp16 transposed vt
    dim3 pg(W_ / 128, M_ / 128, 3);   // (8, 32, 3)
    proj_qkv_kernel<<<pg, 256>>>(inp, wq, bq, wk, bk, wv, bv,
                                 (uint32_t*)q, (uint32_t*)k, (__half*)vt);

    // 2) QK^T (persistent-A) -> fp16 scores
    dim3 qg(S_ / 512, S_ / 128, B_ * H_);   // (2, 8, 64)
    qk_kernel<<<qg, 256>>>((const __half*)q, (const __half*)k, (uint32_t*)sc);

    // 3) head-axis softmax: fp16 scores -> fp16 attn
    head_softmax_kernel<<<(B_ * S_ * S_ / 4) / 256, 256>>>(
        mask, (const uint32_t*)sc, (uint32_t*)at);

    // 4) attn @ V (pure fp16) -> fp16 x
    dim3 ag(1, S_ / 128, B_ * H_);   // (1, 8, 64)
    av_kernel<<<ag, 256>>>((const __half*)at, (const __half*)vt, (uint32_t*)x);

    // 5) output projection (fp16 A, fp32 W) -> fp32 out
    out_kernel<<<pg.x == 0 ? dim3(8, 32) : dim3(8, 32), 256>>>(
        (const __half*)x, wo, bo, out);
}

// round 17
// speedup vs baseline: 3.5275x; 1.0375x over previous
#include <cuda_runtime.h>
#include <cuda_bf16.h>
#include <cuda_fp16.h>
#include <cstdint>

// MaskedAttention: B=4, S=1024, WIDTH=1024, H=16, DH=64
// Head-axis softmax. GEMMs: 1-pass fp16 mma.sync, fp32 accumulate, ldmatrix.x4.
// inp + weights pre-converted to fp16 (identical rounding to in-loop convert)
// -> all GEMM mainloops are pure fp16 loads. qk: persistent-A (K=64).

#define B_ 4
#define S_ 1024
#define W_ 1024
#define H_ 16
#define DH_ 64
#define M_ (B_ * S_)

// ---------------- device scratch (allocation-free rule) --------------------
__device__ __half g_inp16[M_ * W_];
__device__ __half g_wq16[W_ * W_], g_wk16[W_ * W_], g_wv16[W_ * W_], g_wo16[W_ * W_];
__device__ __half g_q[M_ * W_];
__device__ __half g_k[M_ * W_];
__device__ __half g_vt[B_ * H_ * DH_ * S_];           // V transposed [bh][d][s]
__device__ __half g_x[M_ * W_];
__device__ uint32_t g_sc[(size_t)B_ * H_ * S_ * S_ / 2];   // scores fp16 (128MB)
__device__ uint32_t g_at[(size_t)B_ * H_ * S_ * S_ / 2];   // attn   fp16 (128MB)

// ---------------- helpers --------------------------------------------------
__device__ __forceinline__ void mma_f16(float* c, const uint32_t* a, const uint32_t* b) {
    asm volatile(
        "mma.sync.aligned.m16n8k16.row.col.f32.f16.f16.f32 "
        "{%0,%1,%2,%3}, {%4,%5,%6,%7}, {%8,%9}, {%0,%1,%2,%3};"
        : "+f"(c[0]), "+f"(c[1]), "+f"(c[2]), "+f"(c[3])
        : "r"(a[0]), "r"(a[1]), "r"(a[2]), "r"(a[3]), "r"(b[0]), "r"(b[1]));
}

__device__ __forceinline__ void ldsm4(uint32_t* r, uint32_t saddr) {
    asm volatile("ldmatrix.sync.aligned.m8n8.x4.shared.b16 {%0,%1,%2,%3}, [%4];"
                 : "=r"(r[0]), "=r"(r[1]), "=r"(r[2]), "=r"(r[3]) : "r"(saddr));
}

__device__ __forceinline__ uint32_t pack_h2(float x, float y) {
    __half2 p = __halves2half2(__float2half(x), __float2half(y));
    return *reinterpret_cast<uint32_t*>(&p);
}

// ---------------------------------------------------------------------------
// Generic GEMM core: pure fp16 operands, 1-pass fp16 mma, ldmatrix.x4.
// 128(M) x BN(N) tile, K-tile 32, 256 threads (8 warps: 4m x 2n).
// MODE 0: fp32 C. MODE 3: packed fp16 C. MODE 4: runtime (vt? scatter : fp16 C).
// ---------------------------------------------------------------------------
template <int BN, int MODE>
__device__ __forceinline__ void gemm_core(
        const __half* __restrict__ Ah, int lda,
        const __half* __restrict__ Bh, int ldb,
        int K, float scale, const float* __restrict__ bias,
        float* __restrict__ Cf, uint32_t* __restrict__ C16,
        int ldc, __half* __restrict__ vt) {
    constexpr int NT = BN / 16;
    __shared__ uint32_t AsH[128 * 20];
    __shared__ uint32_t BsH[BN * 20];

    const int tid = threadIdx.x;
    const int lane = tid & 31, warp = tid >> 5;
    const int gid = lane >> 2, tig = lane & 3;
    const int wm = warp >> 1, wn = warp & 1;
    const int m0w = wm * 32, n0w = wn * (BN / 2);
    const int row0 = blockIdx.y * 128;
    const int col0 = blockIdx.x * BN;

    const int a_row = m0w + (lane & 15);
    const int a_co  = (lane >> 4) * 4;
    const int b_row = n0w + ((lane >> 4) & 1) * 8 + (lane & 7);
    const int b_co  = ((lane >> 3) & 1) * 4;
    const uint32_t sA = (uint32_t)__cvta_generic_to_shared(AsH);
    const uint32_t sB = (uint32_t)__cvta_generic_to_shared(BsH);

    float acc[2][NT][4] = {};

    for (int k0 = 0; k0 < K; k0 += 32) {
        #pragma unroll
        for (int it = 0; it < 2; it++) {
            int idx = tid + it * 256;
            int r = idx >> 2, ck = idx & 3;
            uint4 t = *(const uint4*)&Ah[(size_t)(row0 + r) * lda + k0 + ck * 8];
            *(uint4*)&AsH[r * 20 + ck * 4] = t;
        }
        #pragma unroll
        for (int it = 0; it < (BN * 4) / 256; it++) {
            int idx = tid + it * 256;
            int r = idx >> 2, ck = idx & 3;
            uint4 t = *(const uint4*)&Bh[(size_t)(col0 + r) * ldb + k0 + ck * 8];
            *(uint4*)&BsH[r * 20 + ck * 4] = t;
        }
        __syncthreads();

        #pragma unroll
        for (int ks = 0; ks < 2; ks++) {
            const int kb = ks * 8;
            uint32_t ah[2][4], bh[NT][2];
            #pragma unroll
            for (int mi = 0; mi < 2; mi++)
                ldsm4(ah[mi], sA + (uint32_t)((a_row + mi * 16) * 20 + kb + a_co) * 4);
            #pragma unroll
            for (int np = 0; np < NT / 2; np++) {
                uint32_t r[4];
                ldsm4(r, sB + (uint32_t)((b_row + np * 16) * 20 + kb + b_co) * 4);
                bh[np * 2][0] = r[0];     bh[np * 2][1] = r[1];
                bh[np * 2 + 1][0] = r[2]; bh[np * 2 + 1][1] = r[3];
            }
            #pragma unroll
            for (int mi = 0; mi < 2; mi++)
                #pragma unroll
                for (int ni = 0; ni < NT; ni++)
                    mma_f16(acc[mi][ni], ah[mi], bh[ni]);
        }
        __syncthreads();
    }

    #pragma unroll
    for (int mi = 0; mi < 2; mi++) {
        #pragma unroll
        for (int ni = 0; ni < NT; ni++) {
            int row = row0 + m0w + mi * 16 + gid;
            int col = col0 + n0w + ni * 8 + tig * 2;
            float b0 = bias ? bias[col] : 0.0f;
            float b1 = bias ? bias[col + 1] : 0.0f;
            float v0 = acc[mi][ni][0] * scale + b0;
            float v1 = acc[mi][ni][1] * scale + b1;
            float v2 = acc[mi][ni][2] * scale + b0;
            float v3 = acc[mi][ni][3] * scale + b1;
            if (MODE == 0) {
                float2 o0 = {v0, v1}, o1 = {v2, v3};
                *(float2*)&Cf[(size_t)row * ldc + col] = o0;
                *(float2*)&Cf[(size_t)(row + 8) * ldc + col] = o1;
            } else if (MODE == 3) {
                C16[((size_t)row * ldc + col) >> 1] = pack_h2(v0, v1);
                C16[((size_t)(row + 8) * ldc + col) >> 1] = pack_h2(v2, v3);
            } else {   // MODE 4: runtime select
                if (vt) {
                    int b = row >> 10, s = row & 1023;
                    int h = col >> 6, d = col & 63;
                    size_t base = ((size_t)(b * 16 + h) * 64 + d) * S_;
                    vt[base + s] = __float2half(v0);
                    vt[base + S_ + s] = __float2half(v1);
                    vt[base + s + 8] = __float2half(v2);
                    vt[base + S_ + s + 8] = __float2half(v3);
                } else {
                    C16[((size_t)row * ldc + col) >> 1] = pack_h2(v0, v1);
                    C16[((size_t)(row + 8) * ldc + col) >> 1] = pack_h2(v2, v3);
                }
            }
        }
    }
}

// ---------------------------------------------------------------------------
// qk: persistent-A kernel (K = DH = 64). Block: 128 q-rows x 512 k-cols.
// ---------------------------------------------------------------------------
__global__ __launch_bounds__(256, 2) void qk_kernel(
        const __half* __restrict__ q, const __half* __restrict__ k,
        uint32_t* __restrict__ sc) {
    constexpr int RS = 36;
    __shared__ uint32_t Ts[128 * RS];

    const int tid = threadIdx.x;
    const int lane = tid & 31, warp = tid >> 5;
    const int gid = lane >> 2, tig = lane & 3;
    const int wm = warp >> 1, wn = warp & 1;
    const int m0w = wm * 32, n0w = wn * 64;
    const int bh = blockIdx.z;
    const int b = bh >> 4, h = bh & 15;
    const int row0 = blockIdx.y * 128;
    const int colbase = blockIdx.x * 512;

    const __half* qb = q + (size_t)b * S_ * W_ + h * DH_;
    const __half* kb = k + (size_t)b * S_ * W_ + h * DH_;
    uint32_t* scb = sc + (size_t)bh * S_ * S_ / 2;

    const int a_row = m0w + (lane & 15);
    const int a_co  = (lane >> 4) * 4;
    const int b_row = n0w + ((lane >> 4) & 1) * 8 + (lane & 7);
    const int b_co  = ((lane >> 3) & 1) * 4;
    const uint32_t sT = (uint32_t)__cvta_generic_to_shared(Ts);

    #pragma unroll
    for (int it = 0; it < 4; it++) {
        int c = tid + it * 256;
        int r = c >> 3, ck = c & 7;
        uint4 t = *(const uint4*)&qb[(size_t)(row0 + r) * W_ + ck * 8];
        *(uint4*)&Ts[r * RS + ck * 4] = t;
    }
    __syncthreads();

    uint32_t ah[2][4][4];
    #pragma unroll
    for (int mi = 0; mi < 2; mi++)
        #pragma unroll
        for (int ks = 0; ks < 4; ks++)
            ldsm4(ah[mi][ks], sT + (uint32_t)((a_row + mi * 16) * RS + ks * 8 + a_co) * 4);

    #pragma unroll 1
    for (int cb = 0; cb < 4; cb++) {
        const int col0 = colbase + cb * 128;
        __syncthreads();
        #pragma unroll
        for (int it = 0; it < 4; it++) {
            int c = tid + it * 256;
            int r = c >> 3, ck = c & 7;
            uint4 t = *(const uint4*)&kb[(size_t)(col0 + r) * W_ + ck * 8];
            *(uint4*)&Ts[r * RS + ck * 4] = t;
        }
        __syncthreads();

        float acc[2][8][4] = {};
        #pragma unroll
        for (int ks = 0; ks < 4; ks++) {
            #pragma unroll
            for (int np = 0; np < 4; np++) {
                uint32_t r[4];
                ldsm4(r, sT + (uint32_t)((b_row + np * 16) * RS + ks * 8 + b_co) * 4);
                uint32_t b0[2] = {r[0], r[1]};
                uint32_t b1[2] = {r[2], r[3]};
                #pragma unroll
                for (int mi = 0; mi < 2; mi++) {
                    mma_f16(acc[mi][np * 2], ah[mi][ks], b0);
                    mma_f16(acc[mi][np * 2 + 1], ah[mi][ks], b1);
                }
            }
        }

        #pragma unroll
        for (int mi = 0; mi < 2; mi++) {
            #pragma unroll
            for (int ni = 0; ni < 8; ni++) {
                int row = row0 + m0w + mi * 16 + gid;
                int col = col0 + n0w + ni * 8 + tig * 2;
                scb[((size_t)row * S_ + col) >> 1] =
                    pack_h2(acc[mi][ni][0] * 0.125f, acc[mi][ni][1] * 0.125f);
                scb[((size_t)(row + 8) * S_ + col) >> 1] =
                    pack_h2(acc[mi][ni][2] * 0.125f, acc[mi][ni][3] * 0.125f);
            }
        }
    }
}

// ---------------- kernel wrappers (2 CTAs/SM) -------------------------------
__global__ __launch_bounds__(256) void f2h_kernel(
        const float* __restrict__ src, uint32_t* __restrict__ dst, int n4) {
    int idx = blockIdx.x * blockDim.x + threadIdx.x;
    if (idx >= n4) return;
    float4 v = ((const float4*)src)[idx];
    uint2 o = {pack_h2(v.x, v.y), pack_h2(v.z, v.w)};
    ((uint2*)dst)[idx] = o;
}

// merged q/k/v projections: blockIdx.z selects weight/bias/output
__global__ __launch_bounds__(256, 2) void proj_qkv_kernel(
        const __half* __restrict__ inp16,
        const __half* __restrict__ wq16, const float* __restrict__ bq,
        const __half* __restrict__ wk16, const float* __restrict__ bk,
        const __half* __restrict__ wv16, const float* __restrict__ bv,
        uint32_t* __restrict__ q16, uint32_t* __restrict__ k16,
        __half* __restrict__ vtp) {
    const __half* Wt; const float* bias;
    uint32_t* C16 = nullptr; __half* vt = nullptr;
    if (blockIdx.z == 0)      { Wt = wq16; bias = bq; C16 = q16; }
    else if (blockIdx.z == 1) { Wt = wk16; bias = bk; C16 = k16; }
    else                      { Wt = wv16; bias = bv; vt = vtp; }
    gemm_core<128, 4>(inp16, W_, Wt, W_, W_, 1.0f, bias,
                      nullptr, C16, W_, vt);
}

__global__ __launch_bounds__(256, 2) void av_kernel(
        const __half* __restrict__ attn, const __half* __restrict__ vt,
        uint32_t* __restrict__ x16) {
    const int bh = blockIdx.z;
    const int b = bh >> 4, h = bh & 15;
    gemm_core<64, 3>(attn + (size_t)bh * S_ * S_, S_,
                     vt + (size_t)bh * DH_ * S_, S_,
                     S_, 1.0f, nullptr,
                     nullptr, x16 + (((size_t)b * S_ * W_ + h * DH_) >> 1),
                     W_, nullptr);
}

__global__ __launch_bounds__(256, 2) void out_kernel(
        const __half* __restrict__ A, const __half* __restrict__ Wt,
        const float* __restrict__ bias, float* __restrict__ C) {
    gemm_core<128, 0>(A, W_, Wt, W_, W_, 1.0f, bias,
                      C, nullptr, W_, nullptr);
}

// ---------------------------------------------------------------------------
// Head-axis softmax: fp16 scores in, fp16 attn out (fp32 math inside).
// ---------------------------------------------------------------------------
__global__ __launch_bounds__(256) void head_softmax_kernel(
        const int* __restrict__ mask, const uint32_t* __restrict__ sc,
        uint32_t* __restrict__ at) {
    const int idx = blockIdx.x * blockDim.x + threadIdx.x;   // over B*S*S/4
    const int b = idx >> 18;
    const int qs4 = idx & ((1 << 18) - 1);
    const size_t base = (size_t)b * H_ * S_ * S_ + (size_t)qs4 * 4;  // halves
    const size_t hs = (size_t)S_ * S_;

    int4 mv = ((const int4*)mask)[idx];
    int ms[4] = {mv.x, mv.y, mv.z, mv.w};

    float v[H_][4];
    #pragma unroll
    for (int h = 0; h < H_; h++) {
        uint2 t = *(const uint2*)&sc[(base + h * hs) >> 1];
        __half2 p0 = *reinterpret_cast<__half2*>(&t.x);
        __half2 p1 = *reinterpret_cast<__half2*>(&t.y);
        v[h][0] = __low2float(p0);  v[h][1] = __high2float(p0);
        v[h][2] = __low2float(p1);  v[h][3] = __high2float(p1);
    }

    #pragma unroll
    for (int l = 0; l < 4; l++) {
        if (ms[l] == 0) {
            #pragma unroll
            for (int h = 0; h < H_; h++) v[h][l] = 1.0f / 16.0f;
        } else {
            float mx = v[0][l];
            #pragma unroll
            for (int h = 1; h < H_; h++) mx = fmaxf(mx, v[h][l]);
            float s = 0.0f;
            #pragma unroll
            for (int h = 0; h < H_; h++) {
                v[h][l] = __expf(v[h][l] - mx);
                s += v[h][l];
            }
            float inv = 1.0f / s;
            #pragma unroll
            for (int h = 0; h < H_; h++) v[h][l] *= inv;
        }
    }

    #pragma unroll
    for (int h = 0; h < H_; h++) {
        uint2 t;
        t.x = pack_h2(v[h][0], v[h][1]);
        t.y = pack_h2(v[h][2], v[h][3]);
        *(uint2*)&at[(base + h * hs) >> 1] = t;
    }
}

// ---------------------------------------------------------------------------
extern "C" void kernel_launch(void* const* d_in, const int* in_sizes, int n_in,
                              void* d_out, int out_size) {
    const float* inp  = (const float*)d_in[0];
    const int*   mask = (const int*)  d_in[1];
    const float* wq   = (const float*)d_in[2];
    const float* bq   = (const float*)d_in[3];
    const float* wk   = (const float*)d_in[4];
    const float* bk   = (const float*)d_in[5];
    const float* wv   = (const float*)d_in[6];
    const float* bv   = (const float*)d_in[7];
    const float* wo   = (const float*)d_in[8];
    const float* bo   = (const float*)d_in[9];
    float* out = (float*)d_out;

    #define SYM(p, s) void* p; cudaGetSymbolAddress(&p, s)
    SYM(inp16, g_inp16);
    SYM(wq16, g_wq16); SYM(wk16, g_wk16); SYM(wv16, g_wv16); SYM(wo16, g_wo16);
    SYM(q, g_q);   SYM(k, g_k);
    SYM(vt, g_vt); SYM(x, g_x);
    SYM(sc, g_sc); SYM(at, g_at);
    #undef SYM

    // 0) pre-convert inp + weights to fp16 (identical rounding to in-loop)
    f2h_kernel<<<(M_ * W_ / 4) / 256, 256>>>(inp, (uint32_t*)inp16, M_ * W_ / 4);
    f2h_kernel<<<(W_ * W_ / 4) / 256, 256>>>(wq, (uint32_t*)wq16, W_ * W_ / 4);
    f2h_kernel<<<(W_ * W_ / 4) / 256, 256>>>(wk, (uint32_t*)wk16, W_ * W_ / 4);
    f2h_kernel<<<(W_ * W_ / 4) / 256, 256>>>(wv, (uint32_t*)wv16, W_ * W_ / 4);
    f2h_kernel<<<(W_ * W_ / 4) / 256, 256>>>(wo, (uint32_t*)wo16, W_ * W_ / 4);

    // 1) merged projections -> fp16 q, k; fp16 transposed vt
    dim3 pg(W_ / 128, M_ / 128, 3);   // (8, 32, 3)
    proj_qkv_kernel<<<pg, 256>>>((const __half*)inp16,
                                 (const __half*)wq16, bq,
                                 (const __half*)wk16, bk,
                                 (const __half*)wv16, bv,
                                 (uint32_t*)q, (uint32_t*)k, (__half*)vt);

    // 2) QK^T (persistent-A) -> fp16 scores
    dim3 qg(S_ / 512, S_ / 128, B_ * H_);   // (2, 8, 64)
    qk_kernel<<<qg, 256>>>((const __half*)q, (const __half*)k, (uint32_t*)sc);

    // 3) head-axis softmax: fp16 scores -> fp16 attn
    head_softmax_kernel<<<(B_ * S_ * S_ / 4) / 256, 256>>>(
        mask, (const uint32_t*)sc, (uint32_t*)at);

    // 4) attn @ V (pure fp16) -> fp16 x
    dim3 ag(1, S_ / 128, B_ * H_);   // (1, 8, 64)
    av_kernel<<<ag, 256>>>((const __half*)at, (const __half*)vt, (uint32_t*)x);

    // 5) output projection (fp16 A, fp16 W) -> fp32 out
    out_kernel<<<dim3(8, 32), 256>>>((const __half*)x, (const __half*)wo16,
                                     bo, out);
}